// round 10
// baseline (speedup 1.0000x reference)
#include <cuda_runtime.h>
#include <math.h>
#include <stdint.h>

#define FDIM 64
#define HIDD 128
#define MSG  64
#define OUTF 64
#define NMAX 50000

// scratch (no cudaMalloc allowed)
__device__ float g_y[NMAX * MSG];            // mailbox max, 12.8 MB
__device__ float2 g_WdecF[16 * 8 * 32];      // mma B-frags for Wdec
__device__ float2 g_WihF[24 * 24 * 32];      // mma B-frags for W_ih (gi)
__device__ float2 g_WhhF[24 * 8 * 32];       // mma B-frags for W_hh (gh)

// ===========================================================================
// helpers
// ===========================================================================
__device__ __forceinline__ uint32_t cvt_tf32(float f) {
    uint32_t r; asm("cvt.rna.tf32.f32 %0, %1;" : "=r"(r) : "f"(f)); return r;
}
__device__ __forceinline__ float tf32f(float f) {
    return __uint_as_float(cvt_tf32(f));
}
// D += A(16x8) * B(8x8), tf32 inputs, f32 accum  (arch-portable: sm_80+)
__device__ __forceinline__ void mma8(float* c, uint32_t a0, uint32_t a1,
                                     uint32_t a2, uint32_t a3,
                                     uint32_t b0, uint32_t b1) {
    asm volatile(
        "mma.sync.aligned.m16n8k8.row.col.f32.tf32.tf32.f32 "
        "{%0,%1,%2,%3}, {%4,%5,%6,%7}, {%8,%9}, {%0,%1,%2,%3};"
        : "+f"(c[0]), "+f"(c[1]), "+f"(c[2]), "+f"(c[3])
        : "r"(a0), "r"(a1), "r"(a2), "r"(a3), "r"(b0), "r"(b1));
}
__device__ __forceinline__ float sigmoidf(float v) {
    return __fdividef(1.0f, 1.0f + __expf(-v));
}

// edge kernel smem layout (bytes)
#define OFF_W1F   0                    // 16 ns x 8 ks x 32 lane x float2 = 32KB
#define OFF_W2F   32768                // 8 ns x 16 ks x 32 lane x float2 = 32KB
#define OFF_SB1   65536                // 128 f
#define OFF_SB2   66048                // 64 f  (14.42695*b2 + 5.28766 folded)
#define OFF_STRIP 66304                // 16 warps x 2112 floats (16 rows x 132, H only)
#define STRIP_F   2112
#define SMEM_EDGE (OFF_STRIP + 16 * STRIP_F * 4)   // 201472

// node kernel smem layout (floats)
#define NOD_STRIP 0                    // 8 warps x 16 x 196
#define NOD_YB    (8 * 3136)           // 8 warps x 16 x 68
#define NOD_ZB    (NOD_YB + 8 * 1088)
#define NOD_BR    (NOD_ZB + 8 * 1088)  // 128: bih+bhh (r,z gates)
#define NOD_BIN   (NOD_BR + 128)       // 64: bih n-gate
#define NOD_BHN   (NOD_BIN + 64)       // 64: bhh n-gate
#define NOD_BDEC  (NOD_BHN + 64)       // 128
#define SMEM_NODE ((NOD_BDEC + 128) * 4)

// ---------------------------------------------------------------------------
// init: zero mailbox + pack node-GEMM weight fragments
// ---------------------------------------------------------------------------
__global__ void init_kernel(const float* __restrict__ W_ih,
                            const float* __restrict__ W_hh,
                            const float* __restrict__ Wdec, int N)
{
    int idx = blockIdx.x * blockDim.x + threadIdx.x;
    if (idx < N * MSG) g_y[idx] = 0.0f;
    int lane = idx & 31, g = lane >> 2, t = lane & 3;
    if (idx < 16 * 8 * 32) {                 // WdecF: B[k=j][n=h] = Wdec[j*128+h]
        int ks = (idx >> 5) & 7, ns = idx >> 8;
        g_WdecF[idx] = make_float2(
            tf32f(Wdec[(ks * 8 + t) * 128 + ns * 8 + g]),
            tf32f(Wdec[(ks * 8 + t + 4) * 128 + ns * 8 + g]));
    }
    if (idx < 24 * 24 * 32) {                // WihF: B[k=i][n=o] = W_ih[o*192+i]
        int ks = (idx >> 5) % 24, ns = (idx >> 5) / 24;
        g_WihF[idx] = make_float2(
            tf32f(W_ih[(ns * 8 + g) * 192 + ks * 8 + t]),
            tf32f(W_ih[(ns * 8 + g) * 192 + ks * 8 + t + 4]));
    }
    if (idx < 24 * 8 * 32) {                 // WhhF: B[k=j][n=o] = W_hh[o*64+j]
        int ks = (idx >> 5) & 7, ns = idx >> 8;
        g_WhhF[idx] = make_float2(
            tf32f(W_hh[(ns * 8 + g) * 64 + ks * 8 + t]),
            tf32f(W_hh[(ns * 8 + g) * 64 + ks * 8 + t + 4]));
    }
}

// ---------------------------------------------------------------------------
// edge kernel (mma.sync tf32): persistent, tile = 256 edges, warp = 16 edges
//   software-pipelined: gather(t+1) issued before GEMM2(t); u prefetched 1 tile ahead
//   GEMM1: H[16,128] = X[16,64] @ W1, relu+bias -> strip (smem)
//   GEMM2: L[16,64]  = H[16,128] @ W2
//   epi:   gumbel softmax in log2 domain + thresholded atomicMax scatter
// ---------------------------------------------------------------------------
__global__ void __launch_bounds__(512, 1)
edge_mma_kernel(const float* __restrict__ x, const int* __restrict__ src,
                const int* __restrict__ dst, const float* __restrict__ u,
                const float* __restrict__ W1, const float* __restrict__ b1,
                const float* __restrict__ W2, const float* __restrict__ b2,
                int E)
{
    extern __shared__ unsigned char smraw[];
    float2* w1f = (float2*)(smraw + OFF_W1F);
    float2* w2f = (float2*)(smraw + OFF_W2F);
    float*  sb1 = (float*)(smraw + OFF_SB1);
    float*  sb2 = (float*)(smraw + OFF_SB2);

    const int tid = threadIdx.x;
    const int warp = tid >> 5, lane = tid & 31;
    const int t = lane & 3, g = lane >> 2;
    const unsigned FULL = 0xffffffffu;
    float* strip = (float*)(smraw + OFF_STRIP) + warp * STRIP_F;

    // ---- pack weights into mma fragment order (tf32-rounded), once
    for (int idx = tid; idx < 16 * 8 * 32; idx += 512) {
        int ln = idx & 31, ks = (idx >> 5) & 7, ns = idx >> 8;
        int tt = ln & 3, gg = ln >> 2;
        w1f[idx] = make_float2(tf32f(W1[(ks * 8 + tt) * 128 + ns * 8 + gg]),
                               tf32f(W1[(ks * 8 + tt + 4) * 128 + ns * 8 + gg]));
    }
    for (int idx = tid; idx < 8 * 16 * 32; idx += 512) {
        int ln = idx & 31, ks = (idx >> 5) & 15, ns = idx >> 9;
        int tt = ln & 3, gg = ln >> 2;
        w2f[idx] = make_float2(tf32f(W2[(ks * 8 + tt) * 64 + ns * 8 + gg]),
                               tf32f(W2[(ks * 8 + tt + 4) * 64 + ns * 8 + gg]));
    }
    if (tid < 128) sb1[tid] = b1[tid];
    // 10/tau*log2e folded into bias; +5.287663 = -10*log2(ln2) from the log-base fold
    if (tid < 64)  sb2[tid] = fmaf(14.42695041f, b2[tid], 5.287663189f);
    __syncthreads();

    const int ntiles = (E + 255) >> 8;
    const int r0 = warp * 16;
    const int stride = gridDim.x;

    float ax0[8], ax1[8], ax2[8], ax3[8];

    // ---- prologue: prefetch u + gather for first tile
    int tile = blockIdx.x;
    if (tile < ntiles) {
        int base = tile << 8;
        {
            int row = lane >> 1, half = (lane & 1) * 32;
            const float* up = u + (size_t)min(base + r0 + row, E - 1) * 64 + half;
            asm volatile("prefetch.global.L2 [%0];" :: "l"(up));
        }
        int el = base + r0 + g;
        int s_lo = src[min(el, E - 1)];
        int s_hi = src[min(el + 8, E - 1)];
        const float* xlo = x + (size_t)s_lo * 64;
        const float* xhi = x + (size_t)s_hi * 64;
        #pragma unroll
        for (int ks = 0; ks < 8; ks++) {
            ax0[ks] = tf32f(xlo[ks * 8 + t]);
            ax1[ks] = tf32f(xhi[ks * 8 + t]);
            ax2[ks] = tf32f(xlo[ks * 8 + t + 4]);
            ax3[ks] = tf32f(xhi[ks * 8 + t + 4]);
        }
    }

    for (; tile < ntiles; tile += stride) {
        const int base = tile << 8;
        const int e_lo = base + r0 + g, e_hi = e_lo + 8;
        __syncwarp();   // strip WAR: prev GEMM2 reads done before epi1 writes

        // ---- GEMM1 in two passes of 8 n-slabs (A in registers)
        #pragma unroll
        for (int pass = 0; pass < 2; pass++) {
            const int nbase = pass * 8;
            float acc[8][4];
            #pragma unroll
            for (int ns = 0; ns < 8; ns++)
                { acc[ns][0] = acc[ns][1] = acc[ns][2] = acc[ns][3] = 0.f; }

            #pragma unroll
            for (int ks = 0; ks < 8; ks++) {
                uint32_t a0 = __float_as_uint(ax0[ks]);
                uint32_t a1 = __float_as_uint(ax1[ks]);
                uint32_t a2 = __float_as_uint(ax2[ks]);
                uint32_t a3 = __float_as_uint(ax3[ks]);
                #pragma unroll
                for (int ns = 0; ns < 8; ns++) {
                    float2 b = w1f[((nbase + ns) * 8 + ks) * 32 + lane];
                    mma8(acc[ns], a0, a1, a2, a3,
                         __float_as_uint(b.x), __float_as_uint(b.y));
                }
            }
            #pragma unroll
            for (int ns = 0; ns < 8; ns++) {
                int c = (nbase + ns) * 8 + 2 * t;
                float bx = sb1[c], by = sb1[c + 1];
                *(float2*)(strip + g * 132 + c) =
                    make_float2(tf32f(fmaxf(acc[ns][0] + bx, 0.f)),
                                tf32f(fmaxf(acc[ns][1] + by, 0.f)));
                *(float2*)(strip + (g + 8) * 132 + c) =
                    make_float2(tf32f(fmaxf(acc[ns][2] + bx, 0.f)),
                                tf32f(fmaxf(acc[ns][3] + by, 0.f)));
            }
        }
        __syncwarp();   // H visible to whole warp before GEMM2

        // ---- pipelined gather + prefetch for NEXT tile (latency hidden by GEMM2/epi)
        {
            int ntile = tile + stride;
            if (ntile < ntiles) {
                int nb = ntile << 8;
                int row = lane >> 1, half = (lane & 1) * 32;
                const float* up = u + (size_t)min(nb + r0 + row, E - 1) * 64 + half;
                asm volatile("prefetch.global.L2 [%0];" :: "l"(up));
                int el = nb + r0 + g;
                int s_lo = src[min(el, E - 1)];
                int s_hi = src[min(el + 8, E - 1)];
                const float* xlo = x + (size_t)s_lo * 64;
                const float* xhi = x + (size_t)s_hi * 64;
                #pragma unroll
                for (int ks = 0; ks < 8; ks++) {
                    ax0[ks] = tf32f(xlo[ks * 8 + t]);
                    ax1[ks] = tf32f(xhi[ks * 8 + t]);
                    ax2[ks] = tf32f(xlo[ks * 8 + t + 4]);
                    ax3[ks] = tf32f(xhi[ks * 8 + t + 4]);
                }
            }
        }

        // ---- GEMM2: L[16,64] = H[16,128] @ W2
        float acc2[8][4];
        #pragma unroll
        for (int ns = 0; ns < 8; ns++)
            { acc2[ns][0] = acc2[ns][1] = acc2[ns][2] = acc2[ns][3] = 0.f; }
        for (int ks = 0; ks < 16; ks++) {
            uint32_t a0 = __float_as_uint(strip[g * 132 + ks * 8 + t]);
            uint32_t a1 = __float_as_uint(strip[(g + 8) * 132 + ks * 8 + t]);
            uint32_t a2 = __float_as_uint(strip[g * 132 + ks * 8 + t + 4]);
            uint32_t a3 = __float_as_uint(strip[(g + 8) * 132 + ks * 8 + t + 4]);
            #pragma unroll
            for (int ns = 0; ns < 8; ns++) {
                float2 b = w2f[(ns * 16 + ks) * 32 + lane];
                mma8(acc2[ns], a0, a1, a2, a3,
                     __float_as_uint(b.x), __float_as_uint(b.y));
            }
        }

        // ---- epi: gumbel softmax in log2 domain.
        //  a = 14.42695*logit + sb2' - 10*log2(min(-log2(u), 33.219))
        {
            const bool vlo = e_lo < E, vhi = e_hi < E;
            float alo[16], ahi[16];
            float mlo = -1e30f, mhi = -1e30f;
            #pragma unroll
            for (int ns = 0; ns < 8; ns++) {
                int c = ns * 8 + 2 * t;
                float b2x = sb2[c], b2y = sb2[c + 1];
                float2 ul = vlo ? *(const float2*)(u + (size_t)e_lo * 64 + c)
                               : make_float2(0.5f, 0.5f);
                float2 uh = vhi ? *(const float2*)(u + (size_t)e_hi * 64 + c)
                               : make_float2(0.5f, 0.5f);
                // p = -log2(u), clamped at 33.219 (== -ln(1e-10) in log2 units)
                float pl0 = fminf(-__log2f(ul.x), 33.21928095f);
                float pl1 = fminf(-__log2f(ul.y), 33.21928095f);
                float ph0 = fminf(-__log2f(uh.x), 33.21928095f);
                float ph1 = fminf(-__log2f(uh.y), 33.21928095f);
                float t00 = fmaf(acc2[ns][0], 14.42695041f, b2x);
                float t01 = fmaf(acc2[ns][1], 14.42695041f, b2y);
                float t10 = fmaf(acc2[ns][2], 14.42695041f, b2x);
                float t11 = fmaf(acc2[ns][3], 14.42695041f, b2y);
                alo[2*ns]   = fmaf(__log2f(pl0), -10.0f, t00);
                alo[2*ns+1] = fmaf(__log2f(pl1), -10.0f, t01);
                ahi[2*ns]   = fmaf(__log2f(ph0), -10.0f, t10);
                ahi[2*ns+1] = fmaf(__log2f(ph1), -10.0f, t11);
                mlo = fmaxf(mlo, fmaxf(alo[2*ns], alo[2*ns+1]));
                mhi = fmaxf(mhi, fmaxf(ahi[2*ns], ahi[2*ns+1]));
            }
            mlo = fmaxf(mlo, __shfl_xor_sync(FULL, mlo, 1));
            mlo = fmaxf(mlo, __shfl_xor_sync(FULL, mlo, 2));
            mhi = fmaxf(mhi, __shfl_xor_sync(FULL, mhi, 1));
            mhi = fmaxf(mhi, __shfl_xor_sync(FULL, mhi, 2));
            float slo = 0.f, shi = 0.f;
            #pragma unroll
            for (int i = 0; i < 16; i++) {
                float dl = alo[i] - mlo, dh = ahi[i] - mhi;
                // 2^-20 < 1e-6 cutoff: predicate off the MUFU + sum + atomic
                alo[i] = (dl > -20.f) ? exp2f(dl) : 0.f;
                ahi[i] = (dh > -20.f) ? exp2f(dh) : 0.f;
                slo += alo[i]; shi += ahi[i];
            }
            slo += __shfl_xor_sync(FULL, slo, 1);
            slo += __shfl_xor_sync(FULL, slo, 2);
            shi += __shfl_xor_sync(FULL, shi, 1);
            shi += __shfl_xor_sync(FULL, shi, 2);
            float ilo = __fdividef(1.0f, slo), ihi = __fdividef(1.0f, shi);
            // softmax strictly positive -> int compare == float compare.
            // skip values < 1e-6: y abs error <= 1e-6, invisible at 1e-3 rel_err
            if (vlo) {
                int* yp = (int*)(g_y + (size_t)dst[e_lo] * 64);
                #pragma unroll
                for (int ns = 0; ns < 8; ns++) {
                    float v0 = alo[2*ns] * ilo, v1 = alo[2*ns+1] * ilo;
                    if (v0 > 1e-6f) atomicMax(yp + ns*8 + 2*t,     __float_as_int(v0));
                    if (v1 > 1e-6f) atomicMax(yp + ns*8 + 2*t + 1, __float_as_int(v1));
                }
            }
            if (vhi) {
                int* yp = (int*)(g_y + (size_t)dst[e_hi] * 64);
                #pragma unroll
                for (int ns = 0; ns < 8; ns++) {
                    float v0 = ahi[2*ns] * ihi, v1 = ahi[2*ns+1] * ihi;
                    if (v0 > 1e-6f) atomicMax(yp + ns*8 + 2*t,     __float_as_int(v0));
                    if (v1 > 1e-6f) atomicMax(yp + ns*8 + 2*t + 1, __float_as_int(v1));
                }
            }
        }
    }
}

// ---------------------------------------------------------------------------
// node kernel (mma.sync tf32): 8 warps/CTA, warp = 16 nodes  (unchanged)
// ---------------------------------------------------------------------------
__global__ void __launch_bounds__(256, 1)
node_kernel(const float* __restrict__ x,
            const float* __restrict__ z,
            const float* __restrict__ bdec,
            const float* __restrict__ bih,
            const float* __restrict__ bhh,
            float* __restrict__ out,
            int N, int HALF, int two)
{
    extern __shared__ float nsm[];
    const int tid = threadIdx.x, warp = tid >> 5, lane = tid & 31;
    const int t = lane & 3, g = lane >> 2;

    float* sbr   = nsm + NOD_BR;
    float* sbin  = nsm + NOD_BIN;
    float* sbhn  = nsm + NOD_BHN;
    float* sbdec = nsm + NOD_BDEC;
    if (tid < 128) sbr[tid] = bih[tid] + bhh[tid];
    if (tid < 64)  { sbin[tid] = bih[128 + tid]; sbhn[tid] = bhh[128 + tid]; }
    if (tid < 128) sbdec[tid] = bdec[tid];
    __syncthreads();

    const int nb = (blockIdx.x * 8 + warp) * 16;
    if (nb >= N) return;

    float* strip = nsm + NOD_STRIP + warp * 3136;   // 16 x 196: x | dec
    float* yb    = nsm + NOD_YB    + warp * 1088;   // 16 x 68 tf32
    float* zb    = nsm + NOD_ZB    + warp * 1088;   // 16 x 68 fp32

    // ---- load x (tf32), y (tf32), z (fp32)
    {
        int r = lane >> 1, ch = (lane & 1) * 32;
        int n = min(nb + r, N - 1);
        const float4* xp = (const float4*)(x + (size_t)n * 64 + ch);
        const float4* yp = (const float4*)(g_y + (size_t)n * 64 + ch);
        const float4* zp = (const float4*)(z + (size_t)n * 64 + ch);
        float* sx = strip + r * 196 + ch;
        float* sy = yb + r * 68 + ch;
        float* sz = zb + r * 68 + ch;
        #pragma unroll
        for (int i = 0; i < 8; i++) {
            float4 vx = xp[i], vy = yp[i], vz = zp[i];
            sx[i*4+0] = tf32f(vx.x); sx[i*4+1] = tf32f(vx.y);
            sx[i*4+2] = tf32f(vx.z); sx[i*4+3] = tf32f(vx.w);
            sy[i*4+0] = tf32f(vy.x); sy[i*4+1] = tf32f(vy.y);
            sy[i*4+2] = tf32f(vy.z); sy[i*4+3] = tf32f(vy.w);
            *(float4*)(sz + i*4) = vz;
        }
    }
    __syncwarp();

    // ---- dec GEMM: 16 accs, ks-outer
    {
        float acc[16][4];
        #pragma unroll
        for (int ns = 0; ns < 16; ns++) {
            int c = ns * 8 + 2 * t;
            acc[ns][0] = sbdec[c]; acc[ns][1] = sbdec[c + 1];
            acc[ns][2] = sbdec[c]; acc[ns][3] = sbdec[c + 1];
        }
        for (int ks = 0; ks < 8; ks++) {
            uint32_t a0 = __float_as_uint(yb[g * 68 + ks * 8 + t]);
            uint32_t a1 = __float_as_uint(yb[(g + 8) * 68 + ks * 8 + t]);
            uint32_t a2 = __float_as_uint(yb[g * 68 + ks * 8 + t + 4]);
            uint32_t a3 = __float_as_uint(yb[(g + 8) * 68 + ks * 8 + t + 4]);
            #pragma unroll
            for (int ns = 0; ns < 16; ns++) {
                float2 b = __ldg(&g_WdecF[(ns * 8 + ks) * 32 + lane]);
                mma8(acc[ns], a0, a1, a2, a3,
                     __float_as_uint(b.x), __float_as_uint(b.y));
            }
        }
        #pragma unroll
        for (int ns = 0; ns < 16; ns++) {
            int c = 64 + ns * 8 + 2 * t;
            strip[g * 196 + c]           = tf32f(fmaxf(acc[ns][0], 0.f));
            strip[g * 196 + c + 1]       = tf32f(fmaxf(acc[ns][1], 0.f));
            strip[(g + 8) * 196 + c]     = tf32f(fmaxf(acc[ns][2], 0.f));
            strip[(g + 8) * 196 + c + 1] = tf32f(fmaxf(acc[ns][3], 0.f));
        }
    }
    __syncwarp();

    // ---- gate passes
    float rg[8][4], zg[8][4], ai[8][4], ah[8][4];

    #pragma unroll
    for (int p = 0; p < 2; p++) {               // p=0: r gate, p=1: z gate
        const int ns0 = p * 8;
        float acc[8][4];
        #pragma unroll
        for (int ns = 0; ns < 8; ns++) {
            int c = (ns0 + ns) * 8 + 2 * t;
            acc[ns][0] = sbr[c]; acc[ns][1] = sbr[c + 1];
            acc[ns][2] = sbr[c]; acc[ns][3] = sbr[c + 1];
        }
        for (int ks = 0; ks < 24; ks++) {       // gi: A = strip(x|dec)
            uint32_t a0 = __float_as_uint(strip[g * 196 + ks * 8 + t]);
            uint32_t a1 = __float_as_uint(strip[(g + 8) * 196 + ks * 8 + t]);
            uint32_t a2 = __float_as_uint(strip[g * 196 + ks * 8 + t + 4]);
            uint32_t a3 = __float_as_uint(strip[(g + 8) * 196 + ks * 8 + t + 4]);
            #pragma unroll
            for (int ns = 0; ns < 8; ns++) {
                float2 b = __ldg(&g_WihF[((ns0 + ns) * 24 + ks) * 32 + lane]);
                mma8(acc[ns], a0, a1, a2, a3,
                     __float_as_uint(b.x), __float_as_uint(b.y));
            }
        }
        for (int ks = 0; ks < 8; ks++) {        // gh: A = z (cvt tf32)
            uint32_t a0 = cvt_tf32(zb[g * 68 + ks * 8 + t]);
            uint32_t a1 = cvt_tf32(zb[(g + 8) * 68 + ks * 8 + t]);
            uint32_t a2 = cvt_tf32(zb[g * 68 + ks * 8 + t + 4]);
            uint32_t a3 = cvt_tf32(zb[(g + 8) * 68 + ks * 8 + t + 4]);
            #pragma unroll
            for (int ns = 0; ns < 8; ns++) {
                float2 b = __ldg(&g_WhhF[((ns0 + ns) * 8 + ks) * 32 + lane]);
                mma8(acc[ns], a0, a1, a2, a3,
                     __float_as_uint(b.x), __float_as_uint(b.y));
            }
        }
        #pragma unroll
        for (int ns = 0; ns < 8; ns++)
            #pragma unroll
            for (int q = 0; q < 4; q++) {
                float s = sigmoidf(acc[ns][q]);
                if (p == 0) rg[ns][q] = s; else zg[ns][q] = s;
            }
    }

    // n gate: i_n and h_n separate
    #pragma unroll
    for (int ns = 0; ns < 8; ns++) {
        int c = ns * 8 + 2 * t;
        ai[ns][0] = sbin[c]; ai[ns][1] = sbin[c + 1];
        ai[ns][2] = sbin[c]; ai[ns][3] = sbin[c + 1];
        ah[ns][0] = sbhn[c]; ah[ns][1] = sbhn[c + 1];
        ah[ns][2] = sbhn[c]; ah[ns][3] = sbhn[c + 1];
    }
    for (int ks = 0; ks < 24; ks++) {
        uint32_t a0 = __float_as_uint(strip[g * 196 + ks * 8 + t]);
        uint32_t a1 = __float_as_uint(strip[(g + 8) * 196 + ks * 8 + t]);
        uint32_t a2 = __float_as_uint(strip[g * 196 + ks * 8 + t + 4]);
        uint32_t a3 = __float_as_uint(strip[(g + 8) * 196 + ks * 8 + t + 4]);
        #pragma unroll
        for (int ns = 0; ns < 8; ns++) {
            float2 b = __ldg(&g_WihF[((16 + ns) * 24 + ks) * 32 + lane]);
            mma8(ai[ns], a0, a1, a2, a3,
                 __float_as_uint(b.x), __float_as_uint(b.y));
        }
    }
    for (int ks = 0; ks < 8; ks++) {
        uint32_t a0 = cvt_tf32(zb[g * 68 + ks * 8 + t]);
        uint32_t a1 = cvt_tf32(zb[(g + 8) * 68 + ks * 8 + t]);
        uint32_t a2 = cvt_tf32(zb[g * 68 + ks * 8 + t + 4]);
        uint32_t a3 = cvt_tf32(zb[(g + 8) * 68 + ks * 8 + t + 4]);
        #pragma unroll
        for (int ns = 0; ns < 8; ns++) {
            float2 b = __ldg(&g_WhhF[((16 + ns) * 8 + ks) * 32 + lane]);
            mma8(ah[ns], a0, a1, a2, a3,
                 __float_as_uint(b.x), __float_as_uint(b.y));
        }
    }

    // ---- combine gates + write (rows nb+g, nb+g+8; cols ns*8+2t, +1)
    const int R0 = nb + g, R1 = nb + g + 8;
    #pragma unroll
    for (int ns = 0; ns < 8; ns++) {
        int o = ns * 8 + 2 * t;
        float n00 = tanhf(ai[ns][0] + rg[ns][0] * ah[ns][0]);
        float n01 = tanhf(ai[ns][1] + rg[ns][1] * ah[ns][1]);
        float n10 = tanhf(ai[ns][2] + rg[ns][2] * ah[ns][2]);
        float n11 = tanhf(ai[ns][3] + rg[ns][3] * ah[ns][3]);
        float z00 = zb[g * 68 + o],       z01 = zb[g * 68 + o + 1];
        float z10 = zb[(g + 8) * 68 + o], z11 = zb[(g + 8) * 68 + o + 1];
        float h00 = (1.f - zg[ns][0]) * n00 + zg[ns][0] * z00;
        float h01 = (1.f - zg[ns][1]) * n01 + zg[ns][1] * z01;
        float h10 = (1.f - zg[ns][2]) * n10 + zg[ns][2] * z10;
        float h11 = (1.f - zg[ns][3]) * n11 + zg[ns][3] * z11;
        if (R0 < N) {
            *(float2*)(out + (size_t)R0 * 64 + o) = make_float2(h00, h01);
            if (two) *(float2*)(out + HALF + (size_t)R0 * 64 + o) = make_float2(h00, h01);
        }
        if (R1 < N) {
            *(float2*)(out + (size_t)R1 * 64 + o) = make_float2(h10, h11);
            if (two) *(float2*)(out + HALF + (size_t)R1 * 64 + o) = make_float2(h10, h11);
        }
    }
}

// ---------------------------------------------------------------------------
// launch
// inputs: x, z, src, dst, u, W_enc1, b_enc1, W_enc2, b_enc2,
//         W_dec, b_dec, W_ih, b_ih, W_hh, b_hh
// ---------------------------------------------------------------------------
extern "C" void kernel_launch(void* const* d_in, const int* in_sizes, int n_in,
                              void* d_out, int out_size)
{
    const float* x     = (const float*)d_in[0];
    const float* z     = (const float*)d_in[1];
    const int*   src   = (const int*)  d_in[2];
    const int*   dst   = (const int*)  d_in[3];
    const float* u     = (const float*)d_in[4];
    const float* W1    = (const float*)d_in[5];
    const float* b1    = (const float*)d_in[6];
    const float* W2    = (const float*)d_in[7];
    const float* b2    = (const float*)d_in[8];
    const float* Wdec  = (const float*)d_in[9];
    const float* bdec  = (const float*)d_in[10];
    const float* Wih   = (const float*)d_in[11];
    const float* bih   = (const float*)d_in[12];
    const float* Whh   = (const float*)d_in[13];
    const float* bhh   = (const float*)d_in[14];

    const int N = in_sizes[0] / FDIM;
    const int E = in_sizes[2];
    float* out = (float*)d_out;
    const int HALF = N * OUTF;
    const int two = (out_size >= 2 * HALF) ? 1 : 0;

    // init mailbox + fragment packs
    {
        int total = N * MSG;
        init_kernel<<<(total + 255) / 256, 256>>>(Wih, Whh, Wdec, N);
    }

    // edge kernel: persistent mma.sync tf32, software-pipelined
    {
        cudaFuncSetAttribute(edge_mma_kernel,
                             cudaFuncAttributeMaxDynamicSharedMemorySize, SMEM_EDGE);
        edge_mma_kernel<<<148, 512, SMEM_EDGE>>>(x, src, dst, u, W1, b1, W2, b2, E);
    }

    // node kernel: mma.sync tf32
    {
        cudaFuncSetAttribute(node_kernel,
                             cudaFuncAttributeMaxDynamicSharedMemorySize, SMEM_NODE);
        int blocks = (N + 127) / 128;
        node_kernel<<<blocks, 256, SMEM_NODE>>>(x, z, bdec, bih, bhh, out, N, HALF, two);
    }
}

// round 11
// speedup vs baseline: 1.5103x; 1.5103x over previous
#include <cuda_runtime.h>
#include <math.h>
#include <stdint.h>

#define FDIM 64
#define HIDD 128
#define MSG  64
#define OUTF 64
#define NMAX 50000

// scratch (no cudaMalloc allowed)
__device__ float g_y[NMAX * MSG];            // mailbox max, 12.8 MB
__device__ float2 g_WdecF[16 * 8 * 32];      // mma B-frags for Wdec
__device__ float2 g_WihF[24 * 24 * 32];      // mma B-frags for W_ih (gi)
__device__ float2 g_WhhF[24 * 8 * 32];       // mma B-frags for W_hh (gh)

// ===========================================================================
// helpers
// ===========================================================================
__device__ __forceinline__ uint32_t cvt_tf32(float f) {
    uint32_t r; asm("cvt.rna.tf32.f32 %0, %1;" : "=r"(r) : "f"(f)); return r;
}
__device__ __forceinline__ float tf32f(float f) {
    return __uint_as_float(cvt_tf32(f));
}
// D += A(16x8) * B(8x8), tf32 inputs, f32 accum  (arch-portable: sm_80+)
__device__ __forceinline__ void mma8(float* c, uint32_t a0, uint32_t a1,
                                     uint32_t a2, uint32_t a3,
                                     uint32_t b0, uint32_t b1) {
    asm volatile(
        "mma.sync.aligned.m16n8k8.row.col.f32.tf32.tf32.f32 "
        "{%0,%1,%2,%3}, {%4,%5,%6,%7}, {%8,%9}, {%0,%1,%2,%3};"
        : "+f"(c[0]), "+f"(c[1]), "+f"(c[2]), "+f"(c[3])
        : "r"(a0), "r"(a1), "r"(a2), "r"(a3), "r"(b0), "r"(b1));
}
__device__ __forceinline__ float sigmoidf(float v) {
    return __fdividef(1.0f, 1.0f + __expf(-v));
}

// edge kernel smem layout (bytes)
#define OFF_W1F   0                    // 16 ns x 8 ks x 32 lane x float2 = 32KB
#define OFF_W2F   32768                // 8 ns x 16 ks x 32 lane x float2 = 32KB
#define OFF_SB1   65536                // 128 f
#define OFF_SB2   66048                // 64 f  (14.42695*b2 + 5.28766 folded)
#define OFF_STRIP 66304                // 16 warps x 2112 floats (16 rows x 132, H only)
#define STRIP_F   2112
#define SMEM_EDGE (OFF_STRIP + 16 * STRIP_F * 4)   // 201472

// node kernel smem layout (floats)
#define NOD_STRIP 0                    // 8 warps x 16 x 196
#define NOD_YB    (8 * 3136)           // 8 warps x 16 x 68
#define NOD_ZB    (NOD_YB + 8 * 1088)
#define NOD_BR    (NOD_ZB + 8 * 1088)  // 128: bih+bhh (r,z gates)
#define NOD_BIN   (NOD_BR + 128)       // 64: bih n-gate
#define NOD_BHN   (NOD_BIN + 64)       // 64: bhh n-gate
#define NOD_BDEC  (NOD_BHN + 64)       // 128
#define SMEM_NODE ((NOD_BDEC + 128) * 4)

// ---------------------------------------------------------------------------
// init: zero mailbox + pack node-GEMM weight fragments
// ---------------------------------------------------------------------------
__global__ void init_kernel(const float* __restrict__ W_ih,
                            const float* __restrict__ W_hh,
                            const float* __restrict__ Wdec, int N)
{
    int idx = blockIdx.x * blockDim.x + threadIdx.x;
    if (idx < N * MSG) g_y[idx] = 0.0f;
    int lane = idx & 31, g = lane >> 2, t = lane & 3;
    if (idx < 16 * 8 * 32) {                 // WdecF: B[k=j][n=h] = Wdec[j*128+h]
        int ks = (idx >> 5) & 7, ns = idx >> 8;
        g_WdecF[idx] = make_float2(
            tf32f(Wdec[(ks * 8 + t) * 128 + ns * 8 + g]),
            tf32f(Wdec[(ks * 8 + t + 4) * 128 + ns * 8 + g]));
    }
    if (idx < 24 * 24 * 32) {                // WihF: B[k=i][n=o] = W_ih[o*192+i]
        int ks = (idx >> 5) % 24, ns = (idx >> 5) / 24;
        g_WihF[idx] = make_float2(
            tf32f(W_ih[(ns * 8 + g) * 192 + ks * 8 + t]),
            tf32f(W_ih[(ns * 8 + g) * 192 + ks * 8 + t + 4]));
    }
    if (idx < 24 * 8 * 32) {                 // WhhF: B[k=j][n=o] = W_hh[o*64+j]
        int ks = (idx >> 5) & 7, ns = idx >> 8;
        g_WhhF[idx] = make_float2(
            tf32f(W_hh[(ns * 8 + g) * 64 + ks * 8 + t]),
            tf32f(W_hh[(ns * 8 + g) * 64 + ks * 8 + t + 4]));
    }
}

// ---------------------------------------------------------------------------
// edge kernel (mma.sync tf32): persistent, tile = 256 edges, warp = 16 edges
//   gather at tile top (short ax liveness -> no spills); NEXT tile's x/u lines
//   warmed via prefetch.global.L2 (zero register cost pipelining)
//   GEMM1: H[16,128] = X[16,64] @ W1, relu+bias -> strip (smem)
//   GEMM2: L[16,64]  = H[16,128] @ W2
//   epi:   gumbel softmax in log2 domain + thresholded atomicMax scatter
// ---------------------------------------------------------------------------
__global__ void __launch_bounds__(512, 1)
edge_mma_kernel(const float* __restrict__ x, const int* __restrict__ src,
                const int* __restrict__ dst, const float* __restrict__ u,
                const float* __restrict__ W1, const float* __restrict__ b1,
                const float* __restrict__ W2, const float* __restrict__ b2,
                int E)
{
    extern __shared__ unsigned char smraw[];
    float2* w1f = (float2*)(smraw + OFF_W1F);
    float2* w2f = (float2*)(smraw + OFF_W2F);
    float*  sb1 = (float*)(smraw + OFF_SB1);
    float*  sb2 = (float*)(smraw + OFF_SB2);

    const int tid = threadIdx.x;
    const int warp = tid >> 5, lane = tid & 31;
    const int t = lane & 3, g = lane >> 2;
    const unsigned FULL = 0xffffffffu;
    float* strip = (float*)(smraw + OFF_STRIP) + warp * STRIP_F;

    // ---- pack weights into mma fragment order (tf32-rounded), once
    for (int idx = tid; idx < 16 * 8 * 32; idx += 512) {
        int ln = idx & 31, ks = (idx >> 5) & 7, ns = idx >> 8;
        int tt = ln & 3, gg = ln >> 2;
        w1f[idx] = make_float2(tf32f(W1[(ks * 8 + tt) * 128 + ns * 8 + gg]),
                               tf32f(W1[(ks * 8 + tt + 4) * 128 + ns * 8 + gg]));
    }
    for (int idx = tid; idx < 8 * 16 * 32; idx += 512) {
        int ln = idx & 31, ks = (idx >> 5) & 15, ns = idx >> 9;
        int tt = ln & 3, gg = ln >> 2;
        w2f[idx] = make_float2(tf32f(W2[(ks * 8 + tt) * 64 + ns * 8 + gg]),
                               tf32f(W2[(ks * 8 + tt + 4) * 64 + ns * 8 + gg]));
    }
    if (tid < 128) sb1[tid] = b1[tid];
    // 10/tau*log2e folded into bias; +5.287663 = -10*log2(ln2) from the log-base fold
    if (tid < 64)  sb2[tid] = fmaf(14.42695041f, b2[tid], 5.287663189f);
    __syncthreads();

    const int ntiles = (E + 255) >> 8;
    const int r0 = warp * 16;
    const int stride = gridDim.x;
    const int prow = lane >> 1;            // prefetch row 0..15
    const int phalf = (lane & 1) * 32;     // prefetch 128B half

    // warm first tile's lines
    if (blockIdx.x < ntiles) {
        int base = blockIdx.x << 8;
        int sp = src[min(base + r0 + prow, E - 1)];
        asm volatile("prefetch.global.L2 [%0];" :: "l"(x + (size_t)sp * 64 + phalf));
        asm volatile("prefetch.global.L2 [%0];"
                     :: "l"(u + (size_t)min(base + r0 + prow, E - 1) * 64 + phalf));
    }

    for (int tile = blockIdx.x; tile < ntiles; tile += stride) {
        const int base = tile << 8;
        const int e_lo = base + r0 + g, e_hi = e_lo + 8;
        __syncwarp();   // strip WAR: prev GEMM2 reads done before epi1 writes

        // ---- next-tile src index (LDG hidden under GEMM1; 1 reg)
        const int ntile = tile + stride;
        int s_next = 0;
        if (ntile < ntiles)
            s_next = src[min((ntile << 8) + r0 + prow, E - 1)];

        // ---- gather x[src] directly into A-fragment registers (L2-warm)
        float ax0[8], ax1[8], ax2[8], ax3[8];
        {
            int s_lo = src[min(e_lo, E - 1)];
            int s_hi = src[min(e_hi, E - 1)];
            const float* xlo = x + (size_t)s_lo * 64;
            const float* xhi = x + (size_t)s_hi * 64;
            #pragma unroll
            for (int ks = 0; ks < 8; ks++) {
                ax0[ks] = tf32f(xlo[ks * 8 + t]);
                ax1[ks] = tf32f(xhi[ks * 8 + t]);
                ax2[ks] = tf32f(xlo[ks * 8 + t + 4]);
                ax3[ks] = tf32f(xhi[ks * 8 + t + 4]);
            }
        }

        // ---- GEMM1 in two passes of 8 n-slabs (A in registers)
        #pragma unroll
        for (int pass = 0; pass < 2; pass++) {
            const int nbase = pass * 8;
            float acc[8][4];
            #pragma unroll
            for (int ns = 0; ns < 8; ns++)
                { acc[ns][0] = acc[ns][1] = acc[ns][2] = acc[ns][3] = 0.f; }

            #pragma unroll
            for (int ks = 0; ks < 8; ks++) {
                uint32_t a0 = __float_as_uint(ax0[ks]);
                uint32_t a1 = __float_as_uint(ax1[ks]);
                uint32_t a2 = __float_as_uint(ax2[ks]);
                uint32_t a3 = __float_as_uint(ax3[ks]);
                #pragma unroll
                for (int ns = 0; ns < 8; ns++) {
                    float2 b = w1f[((nbase + ns) * 8 + ks) * 32 + lane];
                    mma8(acc[ns], a0, a1, a2, a3,
                         __float_as_uint(b.x), __float_as_uint(b.y));
                }
            }
            #pragma unroll
            for (int ns = 0; ns < 8; ns++) {
                int c = (nbase + ns) * 8 + 2 * t;
                float bx = sb1[c], by = sb1[c + 1];
                *(float2*)(strip + g * 132 + c) =
                    make_float2(tf32f(fmaxf(acc[ns][0] + bx, 0.f)),
                                tf32f(fmaxf(acc[ns][1] + by, 0.f)));
                *(float2*)(strip + (g + 8) * 132 + c) =
                    make_float2(tf32f(fmaxf(acc[ns][2] + bx, 0.f)),
                                tf32f(fmaxf(acc[ns][3] + by, 0.f)));
            }
        }
        __syncwarp();   // H visible to whole warp before GEMM2

        // ---- warm NEXT tile's x and u lines (no registers held)
        if (ntile < ntiles) {
            asm volatile("prefetch.global.L2 [%0];"
                         :: "l"(x + (size_t)s_next * 64 + phalf));
            asm volatile("prefetch.global.L2 [%0];"
                         :: "l"(u + (size_t)min((ntile << 8) + r0 + prow, E - 1) * 64 + phalf));
        }

        // ---- GEMM2: L[16,64] = H[16,128] @ W2
        float acc2[8][4];
        #pragma unroll
        for (int ns = 0; ns < 8; ns++)
            { acc2[ns][0] = acc2[ns][1] = acc2[ns][2] = acc2[ns][3] = 0.f; }
        for (int ks = 0; ks < 16; ks++) {
            uint32_t a0 = __float_as_uint(strip[g * 132 + ks * 8 + t]);
            uint32_t a1 = __float_as_uint(strip[(g + 8) * 132 + ks * 8 + t]);
            uint32_t a2 = __float_as_uint(strip[g * 132 + ks * 8 + t + 4]);
            uint32_t a3 = __float_as_uint(strip[(g + 8) * 132 + ks * 8 + t + 4]);
            #pragma unroll
            for (int ns = 0; ns < 8; ns++) {
                float2 b = w2f[(ns * 16 + ks) * 32 + lane];
                mma8(acc2[ns], a0, a1, a2, a3,
                     __float_as_uint(b.x), __float_as_uint(b.y));
            }
        }

        // ---- epi: gumbel softmax in log2 domain.
        //  a = 14.42695*logit + sb2' - 10*log2(min(-log2(u), 33.219))
        {
            const bool vlo = e_lo < E, vhi = e_hi < E;
            float alo[16], ahi[16];
            float mlo = -1e30f, mhi = -1e30f;
            #pragma unroll
            for (int ns = 0; ns < 8; ns++) {
                int c = ns * 8 + 2 * t;
                float b2x = sb2[c], b2y = sb2[c + 1];
                float2 ul = vlo ? *(const float2*)(u + (size_t)e_lo * 64 + c)
                               : make_float2(0.5f, 0.5f);
                float2 uh = vhi ? *(const float2*)(u + (size_t)e_hi * 64 + c)
                               : make_float2(0.5f, 0.5f);
                // p = -log2(u), clamped at 33.219 (== -ln(1e-10) in log2 units)
                float pl0 = fminf(-__log2f(ul.x), 33.21928095f);
                float pl1 = fminf(-__log2f(ul.y), 33.21928095f);
                float ph0 = fminf(-__log2f(uh.x), 33.21928095f);
                float ph1 = fminf(-__log2f(uh.y), 33.21928095f);
                float t00 = fmaf(acc2[ns][0], 14.42695041f, b2x);
                float t01 = fmaf(acc2[ns][1], 14.42695041f, b2y);
                float t10 = fmaf(acc2[ns][2], 14.42695041f, b2x);
                float t11 = fmaf(acc2[ns][3], 14.42695041f, b2y);
                alo[2*ns]   = fmaf(__log2f(pl0), -10.0f, t00);
                alo[2*ns+1] = fmaf(__log2f(pl1), -10.0f, t01);
                ahi[2*ns]   = fmaf(__log2f(ph0), -10.0f, t10);
                ahi[2*ns+1] = fmaf(__log2f(ph1), -10.0f, t11);
                mlo = fmaxf(mlo, fmaxf(alo[2*ns], alo[2*ns+1]));
                mhi = fmaxf(mhi, fmaxf(ahi[2*ns], ahi[2*ns+1]));
            }
            mlo = fmaxf(mlo, __shfl_xor_sync(FULL, mlo, 1));
            mlo = fmaxf(mlo, __shfl_xor_sync(FULL, mlo, 2));
            mhi = fmaxf(mhi, __shfl_xor_sync(FULL, mhi, 1));
            mhi = fmaxf(mhi, __shfl_xor_sync(FULL, mhi, 2));
            float slo = 0.f, shi = 0.f;
            #pragma unroll
            for (int i = 0; i < 16; i++) {
                float dl = alo[i] - mlo, dh = ahi[i] - mhi;
                // 2^-20 < 1e-6 cutoff: predicate off the MUFU + sum + atomic
                alo[i] = (dl > -20.f) ? exp2f(dl) : 0.f;
                ahi[i] = (dh > -20.f) ? exp2f(dh) : 0.f;
                slo += alo[i]; shi += ahi[i];
            }
            slo += __shfl_xor_sync(FULL, slo, 1);
            slo += __shfl_xor_sync(FULL, slo, 2);
            shi += __shfl_xor_sync(FULL, shi, 1);
            shi += __shfl_xor_sync(FULL, shi, 2);
            float ilo = __fdividef(1.0f, slo), ihi = __fdividef(1.0f, shi);
            // softmax strictly positive -> int compare == float compare.
            // skip values < 1e-6: y abs error <= 1e-6, invisible at 1e-3 rel_err
            if (vlo) {
                int* yp = (int*)(g_y + (size_t)dst[e_lo] * 64);
                #pragma unroll
                for (int ns = 0; ns < 8; ns++) {
                    float v0 = alo[2*ns] * ilo, v1 = alo[2*ns+1] * ilo;
                    if (v0 > 1e-6f) atomicMax(yp + ns*8 + 2*t,     __float_as_int(v0));
                    if (v1 > 1e-6f) atomicMax(yp + ns*8 + 2*t + 1, __float_as_int(v1));
                }
            }
            if (vhi) {
                int* yp = (int*)(g_y + (size_t)dst[e_hi] * 64);
                #pragma unroll
                for (int ns = 0; ns < 8; ns++) {
                    float v0 = ahi[2*ns] * ihi, v1 = ahi[2*ns+1] * ihi;
                    if (v0 > 1e-6f) atomicMax(yp + ns*8 + 2*t,     __float_as_int(v0));
                    if (v1 > 1e-6f) atomicMax(yp + ns*8 + 2*t + 1, __float_as_int(v1));
                }
            }
        }
    }
}

// ---------------------------------------------------------------------------
// node kernel (mma.sync tf32): 8 warps/CTA, warp = 16 nodes  (unchanged)
// ---------------------------------------------------------------------------
__global__ void __launch_bounds__(256, 1)
node_kernel(const float* __restrict__ x,
            const float* __restrict__ z,
            const float* __restrict__ bdec,
            const float* __restrict__ bih,
            const float* __restrict__ bhh,
            float* __restrict__ out,
            int N, int HALF, int two)
{
    extern __shared__ float nsm[];
    const int tid = threadIdx.x, warp = tid >> 5, lane = tid & 31;
    const int t = lane & 3, g = lane >> 2;

    float* sbr   = nsm + NOD_BR;
    float* sbin  = nsm + NOD_BIN;
    float* sbhn  = nsm + NOD_BHN;
    float* sbdec = nsm + NOD_BDEC;
    if (tid < 128) sbr[tid] = bih[tid] + bhh[tid];
    if (tid < 64)  { sbin[tid] = bih[128 + tid]; sbhn[tid] = bhh[128 + tid]; }
    if (tid < 128) sbdec[tid] = bdec[tid];
    __syncthreads();

    const int nb = (blockIdx.x * 8 + warp) * 16;
    if (nb >= N) return;

    float* strip = nsm + NOD_STRIP + warp * 3136;   // 16 x 196: x | dec
    float* yb    = nsm + NOD_YB    + warp * 1088;   // 16 x 68 tf32
    float* zb    = nsm + NOD_ZB    + warp * 1088;   // 16 x 68 fp32

    // ---- load x (tf32), y (tf32), z (fp32)
    {
        int r = lane >> 1, ch = (lane & 1) * 32;
        int n = min(nb + r, N - 1);
        const float4* xp = (const float4*)(x + (size_t)n * 64 + ch);
        const float4* yp = (const float4*)(g_y + (size_t)n * 64 + ch);
        const float4* zp = (const float4*)(z + (size_t)n * 64 + ch);
        float* sx = strip + r * 196 + ch;
        float* sy = yb + r * 68 + ch;
        float* sz = zb + r * 68 + ch;
        #pragma unroll
        for (int i = 0; i < 8; i++) {
            float4 vx = xp[i], vy = yp[i], vz = zp[i];
            sx[i*4+0] = tf32f(vx.x); sx[i*4+1] = tf32f(vx.y);
            sx[i*4+2] = tf32f(vx.z); sx[i*4+3] = tf32f(vx.w);
            sy[i*4+0] = tf32f(vy.x); sy[i*4+1] = tf32f(vy.y);
            sy[i*4+2] = tf32f(vy.z); sy[i*4+3] = tf32f(vy.w);
            *(float4*)(sz + i*4) = vz;
        }
    }
    __syncwarp();

    // ---- dec GEMM: 16 accs, ks-outer
    {
        float acc[16][4];
        #pragma unroll
        for (int ns = 0; ns < 16; ns++) {
            int c = ns * 8 + 2 * t;
            acc[ns][0] = sbdec[c]; acc[ns][1] = sbdec[c + 1];
            acc[ns][2] = sbdec[c]; acc[ns][3] = sbdec[c + 1];
        }
        for (int ks = 0; ks < 8; ks++) {
            uint32_t a0 = __float_as_uint(yb[g * 68 + ks * 8 + t]);
            uint32_t a1 = __float_as_uint(yb[(g + 8) * 68 + ks * 8 + t]);
            uint32_t a2 = __float_as_uint(yb[g * 68 + ks * 8 + t + 4]);
            uint32_t a3 = __float_as_uint(yb[(g + 8) * 68 + ks * 8 + t + 4]);
            #pragma unroll
            for (int ns = 0; ns < 16; ns++) {
                float2 b = __ldg(&g_WdecF[(ns * 8 + ks) * 32 + lane]);
                mma8(acc[ns], a0, a1, a2, a3,
                     __float_as_uint(b.x), __float_as_uint(b.y));
            }
        }
        #pragma unroll
        for (int ns = 0; ns < 16; ns++) {
            int c = 64 + ns * 8 + 2 * t;
            strip[g * 196 + c]           = tf32f(fmaxf(acc[ns][0], 0.f));
            strip[g * 196 + c + 1]       = tf32f(fmaxf(acc[ns][1], 0.f));
            strip[(g + 8) * 196 + c]     = tf32f(fmaxf(acc[ns][2], 0.f));
            strip[(g + 8) * 196 + c + 1] = tf32f(fmaxf(acc[ns][3], 0.f));
        }
    }
    __syncwarp();

    // ---- gate passes
    float rg[8][4], zg[8][4], ai[8][4], ah[8][4];

    #pragma unroll
    for (int p = 0; p < 2; p++) {               // p=0: r gate, p=1: z gate
        const int ns0 = p * 8;
        float acc[8][4];
        #pragma unroll
        for (int ns = 0; ns < 8; ns++) {
            int c = (ns0 + ns) * 8 + 2 * t;
            acc[ns][0] = sbr[c]; acc[ns][1] = sbr[c + 1];
            acc[ns][2] = sbr[c]; acc[ns][3] = sbr[c + 1];
        }
        for (int ks = 0; ks < 24; ks++) {       // gi: A = strip(x|dec)
            uint32_t a0 = __float_as_uint(strip[g * 196 + ks * 8 + t]);
            uint32_t a1 = __float_as_uint(strip[(g + 8) * 196 + ks * 8 + t]);
            uint32_t a2 = __float_as_uint(strip[g * 196 + ks * 8 + t + 4]);
            uint32_t a3 = __float_as_uint(strip[(g + 8) * 196 + ks * 8 + t + 4]);
            #pragma unroll
            for (int ns = 0; ns < 8; ns++) {
                float2 b = __ldg(&g_WihF[((ns0 + ns) * 24 + ks) * 32 + lane]);
                mma8(acc[ns], a0, a1, a2, a3,
                     __float_as_uint(b.x), __float_as_uint(b.y));
            }
        }
        for (int ks = 0; ks < 8; ks++) {        // gh: A = z (cvt tf32)
            uint32_t a0 = cvt_tf32(zb[g * 68 + ks * 8 + t]);
            uint32_t a1 = cvt_tf32(zb[(g + 8) * 68 + ks * 8 + t]);
            uint32_t a2 = cvt_tf32(zb[g * 68 + ks * 8 + t + 4]);
            uint32_t a3 = cvt_tf32(zb[(g + 8) * 68 + ks * 8 + t + 4]);
            #pragma unroll
            for (int ns = 0; ns < 8; ns++) {
                float2 b = __ldg(&g_WhhF[((ns0 + ns) * 8 + ks) * 32 + lane]);
                mma8(acc[ns], a0, a1, a2, a3,
                     __float_as_uint(b.x), __float_as_uint(b.y));
            }
        }
        #pragma unroll
        for (int ns = 0; ns < 8; ns++)
            #pragma unroll
            for (int q = 0; q < 4; q++) {
                float s = sigmoidf(acc[ns][q]);
                if (p == 0) rg[ns][q] = s; else zg[ns][q] = s;
            }
    }

    // n gate: i_n and h_n separate
    #pragma unroll
    for (int ns = 0; ns < 8; ns++) {
        int c = ns * 8 + 2 * t;
        ai[ns][0] = sbin[c]; ai[ns][1] = sbin[c + 1];
        ai[ns][2] = sbin[c]; ai[ns][3] = sbin[c + 1];
        ah[ns][0] = sbhn[c]; ah[ns][1] = sbhn[c + 1];
        ah[ns][2] = sbhn[c]; ah[ns][3] = sbhn[c + 1];
    }
    for (int ks = 0; ks < 24; ks++) {
        uint32_t a0 = __float_as_uint(strip[g * 196 + ks * 8 + t]);
        uint32_t a1 = __float_as_uint(strip[(g + 8) * 196 + ks * 8 + t]);
        uint32_t a2 = __float_as_uint(strip[g * 196 + ks * 8 + t + 4]);
        uint32_t a3 = __float_as_uint(strip[(g + 8) * 196 + ks * 8 + t + 4]);
        #pragma unroll
        for (int ns = 0; ns < 8; ns++) {
            float2 b = __ldg(&g_WihF[((16 + ns) * 24 + ks) * 32 + lane]);
            mma8(ai[ns], a0, a1, a2, a3,
                 __float_as_uint(b.x), __float_as_uint(b.y));
        }
    }
    for (int ks = 0; ks < 8; ks++) {
        uint32_t a0 = cvt_tf32(zb[g * 68 + ks * 8 + t]);
        uint32_t a1 = cvt_tf32(zb[(g + 8) * 68 + ks * 8 + t]);
        uint32_t a2 = cvt_tf32(zb[g * 68 + ks * 8 + t + 4]);
        uint32_t a3 = cvt_tf32(zb[(g + 8) * 68 + ks * 8 + t + 4]);
        #pragma unroll
        for (int ns = 0; ns < 8; ns++) {
            float2 b = __ldg(&g_WhhF[((16 + ns) * 8 + ks) * 32 + lane]);
            mma8(ah[ns], a0, a1, a2, a3,
                 __float_as_uint(b.x), __float_as_uint(b.y));
        }
    }

    // ---- combine gates + write (rows nb+g, nb+g+8; cols ns*8+2t, +1)
    const int R0 = nb + g, R1 = nb + g + 8;
    #pragma unroll
    for (int ns = 0; ns < 8; ns++) {
        int o = ns * 8 + 2 * t;
        float n00 = tanhf(ai[ns][0] + rg[ns][0] * ah[ns][0]);
        float n01 = tanhf(ai[ns][1] + rg[ns][1] * ah[ns][1]);
        float n10 = tanhf(ai[ns][2] + rg[ns][2] * ah[ns][2]);
        float n11 = tanhf(ai[ns][3] + rg[ns][3] * ah[ns][3]);
        float z00 = zb[g * 68 + o],       z01 = zb[g * 68 + o + 1];
        float z10 = zb[(g + 8) * 68 + o], z11 = zb[(g + 8) * 68 + o + 1];
        float h00 = (1.f - zg[ns][0]) * n00 + zg[ns][0] * z00;
        float h01 = (1.f - zg[ns][1]) * n01 + zg[ns][1] * z01;
        float h10 = (1.f - zg[ns][2]) * n10 + zg[ns][2] * z10;
        float h11 = (1.f - zg[ns][3]) * n11 + zg[ns][3] * z11;
        if (R0 < N) {
            *(float2*)(out + (size_t)R0 * 64 + o) = make_float2(h00, h01);
            if (two) *(float2*)(out + HALF + (size_t)R0 * 64 + o) = make_float2(h00, h01);
        }
        if (R1 < N) {
            *(float2*)(out + (size_t)R1 * 64 + o) = make_float2(h10, h11);
            if (two) *(float2*)(out + HALF + (size_t)R1 * 64 + o) = make_float2(h10, h11);
        }
    }
}

// ---------------------------------------------------------------------------
// launch
// inputs: x, z, src, dst, u, W_enc1, b_enc1, W_enc2, b_enc2,
//         W_dec, b_dec, W_ih, b_ih, W_hh, b_hh
// ---------------------------------------------------------------------------
extern "C" void kernel_launch(void* const* d_in, const int* in_sizes, int n_in,
                              void* d_out, int out_size)
{
    const float* x     = (const float*)d_in[0];
    const float* z     = (const float*)d_in[1];
    const int*   src   = (const int*)  d_in[2];
    const int*   dst   = (const int*)  d_in[3];
    const float* u     = (const float*)d_in[4];
    const float* W1    = (const float*)d_in[5];
    const float* b1    = (const float*)d_in[6];
    const float* W2    = (const float*)d_in[7];
    const float* b2    = (const float*)d_in[8];
    const float* Wdec  = (const float*)d_in[9];
    const float* bdec  = (const float*)d_in[10];
    const float* Wih   = (const float*)d_in[11];
    const float* bih   = (const float*)d_in[12];
    const float* Whh   = (const float*)d_in[13];
    const float* bhh   = (const float*)d_in[14];

    const int N = in_sizes[0] / FDIM;
    const int E = in_sizes[2];
    float* out = (float*)d_out;
    const int HALF = N * OUTF;
    const int two = (out_size >= 2 * HALF) ? 1 : 0;

    // init mailbox + fragment packs
    {
        int total = N * MSG;
        init_kernel<<<(total + 255) / 256, 256>>>(Wih, Whh, Wdec, N);
    }

    // edge kernel: persistent mma.sync tf32, prefetch-pipelined
    {
        cudaFuncSetAttribute(edge_mma_kernel,
                             cudaFuncAttributeMaxDynamicSharedMemorySize, SMEM_EDGE);
        edge_mma_kernel<<<148, 512, SMEM_EDGE>>>(x, src, dst, u, W1, b1, W2, b2, E);
    }

    // node kernel: mma.sync tf32
    {
        cudaFuncSetAttribute(node_kernel,
                             cudaFuncAttributeMaxDynamicSharedMemorySize, SMEM_NODE);
        int blocks = (N + 127) / 128;
        node_kernel<<<blocks, 256, SMEM_NODE>>>(x, z, bdec, bih, bhh, out, N, HALF, two);
    }
}

// round 14
// speedup vs baseline: 1.9986x; 1.3233x over previous
#include <cuda_runtime.h>
#include <cuda_fp16.h>
#include <math.h>
#include <stdint.h>

#define FDIM 64
#define HIDD 128
#define MSG  64
#define OUTF 64
#define NMAX 50000

// scratch (no cudaMalloc allowed)
__device__ float g_y[NMAX * MSG];            // mailbox max, 12.8 MB
__device__ float2 g_WdecF[16 * 8 * 32];      // mma B-frags for Wdec (tf32)
__device__ float2 g_WihF[24 * 24 * 32];      // mma B-frags for W_ih (gi)
__device__ float2 g_WhhF[24 * 8 * 32];       // mma B-frags for W_hh (gh)

// ===========================================================================
// helpers
// ===========================================================================
__device__ __forceinline__ uint32_t cvt_tf32(float f) {
    uint32_t r; asm("cvt.rna.tf32.f32 %0, %1;" : "=r"(r) : "f"(f)); return r;
}
__device__ __forceinline__ float tf32f(float f) {
    return __uint_as_float(cvt_tf32(f));
}
__device__ __forceinline__ uint32_t pack_h2(float a, float b) {
    __half2 h = __floats2half2_rn(a, b);
    return *reinterpret_cast<uint32_t*>(&h);
}
// D += A(16x8) * B(8x8), tf32 inputs, f32 accum  (node kernel)
__device__ __forceinline__ void mma8(float* c, uint32_t a0, uint32_t a1,
                                     uint32_t a2, uint32_t a3,
                                     uint32_t b0, uint32_t b1) {
    asm volatile(
        "mma.sync.aligned.m16n8k8.row.col.f32.tf32.tf32.f32 "
        "{%0,%1,%2,%3}, {%4,%5,%6,%7}, {%8,%9}, {%0,%1,%2,%3};"
        : "+f"(c[0]), "+f"(c[1]), "+f"(c[2]), "+f"(c[3])
        : "r"(a0), "r"(a1), "r"(a2), "r"(a3), "r"(b0), "r"(b1));
}
// D += A(16x16) * B(16x8), fp16 inputs, f32 accum  (edge kernel; full-rate HMMA)
__device__ __forceinline__ void mma16(float* c, uint32_t a0, uint32_t a1,
                                      uint32_t a2, uint32_t a3,
                                      uint32_t b0, uint32_t b1) {
    asm volatile(
        "mma.sync.aligned.m16n8k16.row.col.f32.f16.f16.f32 "
        "{%0,%1,%2,%3}, {%4,%5,%6,%7}, {%8,%9}, {%0,%1,%2,%3};"
        : "+f"(c[0]), "+f"(c[1]), "+f"(c[2]), "+f"(c[3])
        : "r"(a0), "r"(a1), "r"(a2), "r"(a3), "r"(b0), "r"(b1));
}
__device__ __forceinline__ float sigmoidf(float v) {
    return __fdividef(1.0f, 1.0f + __expf(-v));
}

// edge kernel smem layout (bytes)
#define OFF_W1F   0                    // 16 ns x 4 ks x 32 lane x uint2 = 16KB
#define OFF_W2F   16384                // 8 ns x 8 ks x 32 lane x uint2 = 16KB
#define OFF_SB1   32768                // 128 f
#define OFF_SB2   33280                // 64 f  (14.42695*b2 + 5.28766 folded)
#define OFF_STRIP 33536                // 16 warps x (16 rows x 272B) fp16 H
#define STRIP_B   4352                 // bytes per warp strip
#define STRIP_H   136                  // halves per row (128 + 8 pad)
#define SMEM_EDGE (OFF_STRIP + 16 * STRIP_B)   // 103168

// node kernel smem layout (floats)
#define NOD_STRIP 0                    // 8 warps x 16 x 196
#define NOD_YB    (8 * 3136)           // 8 warps x 16 x 68
#define NOD_ZB    (NOD_YB + 8 * 1088)
#define NOD_BR    (NOD_ZB + 8 * 1088)  // 128: bih+bhh (r,z gates)
#define NOD_BIN   (NOD_BR + 128)       // 64: bih n-gate
#define NOD_BHN   (NOD_BIN + 64)       // 64: bhh n-gate
#define NOD_BDEC  (NOD_BHN + 64)       // 128
#define SMEM_NODE ((NOD_BDEC + 128) * 4)

// ---------------------------------------------------------------------------
// init: zero mailbox + pack node-GEMM weight fragments
// ---------------------------------------------------------------------------
__global__ void init_kernel(const float* __restrict__ W_ih,
                            const float* __restrict__ W_hh,
                            const float* __restrict__ Wdec, int N)
{
    int idx = blockIdx.x * blockDim.x + threadIdx.x;
    if (idx < N * MSG) g_y[idx] = 0.0f;
    int lane = idx & 31, g = lane >> 2, t = lane & 3;
    if (idx < 16 * 8 * 32) {                 // WdecF: B[k=j][n=h] = Wdec[j*128+h]
        int ks = (idx >> 5) & 7, ns = idx >> 8;
        g_WdecF[idx] = make_float2(
            tf32f(Wdec[(ks * 8 + t) * 128 + ns * 8 + g]),
            tf32f(Wdec[(ks * 8 + t + 4) * 128 + ns * 8 + g]));
    }
    if (idx < 24 * 24 * 32) {                // WihF: B[k=i][n=o] = W_ih[o*192+i]
        int ks = (idx >> 5) % 24, ns = (idx >> 5) / 24;
        g_WihF[idx] = make_float2(
            tf32f(W_ih[(ns * 8 + g) * 192 + ks * 8 + t]),
            tf32f(W_ih[(ns * 8 + g) * 192 + ks * 8 + t + 4]));
    }
    if (idx < 24 * 8 * 32) {                 // WhhF: B[k=j][n=o] = W_hh[o*64+j]
        int ks = (idx >> 5) & 7, ns = idx >> 8;
        g_WhhF[idx] = make_float2(
            tf32f(W_hh[(ns * 8 + g) * 64 + ks * 8 + t]),
            tf32f(W_hh[(ns * 8 + g) * 64 + ks * 8 + t + 4]));
    }
}

// ---------------------------------------------------------------------------
// edge kernel (mma.sync fp16 m16n8k16): persistent, tile = 256 edges, warp = 16
//   fp16 mantissa (11 bit) == tf32 mantissa; values O(1); accum fp32 -> same
//   accuracy, half the mma instructions, full-rate HMMA, half the LDS traffic
//   GEMM1: H[16,128] = X[16,64] @ W1 (4 k-steps), relu+bias -> fp16 strip
//   GEMM2: L[16,64]  = H[16,128] @ W2 (8 k-steps)
//   epi:   gumbel softmax in log2 domain + thresholded atomicMax scatter
// ---------------------------------------------------------------------------
__global__ void __launch_bounds__(512, 1)
edge_mma_kernel(const float* __restrict__ x, const int* __restrict__ src,
                const int* __restrict__ dst, const float* __restrict__ u,
                const float* __restrict__ W1, const float* __restrict__ b1,
                const float* __restrict__ W2, const float* __restrict__ b2,
                int E)
{
    extern __shared__ unsigned char smraw[];
    uint2* w1f = (uint2*)(smraw + OFF_W1F);
    uint2* w2f = (uint2*)(smraw + OFF_W2F);
    float* sb1 = (float*)(smraw + OFF_SB1);
    float* sb2 = (float*)(smraw + OFF_SB2);

    const int tid = threadIdx.x;
    const int warp = tid >> 5, lane = tid & 31;
    const int t = lane & 3, g = lane >> 2;
    const unsigned FULL = 0xffffffffu;
    __half* strip = (__half*)(smraw + OFF_STRIP + warp * STRIP_B);

    // ---- pack weights into m16n8k16 B-fragment order (fp16), once
    // b0 = {B[k0][n], B[k0+1][n]}, b1 = {B[k0+8][n], B[k0+9][n]}, k0 = ks*16+2t
    for (int idx = tid; idx < 16 * 4 * 32; idx += 512) {       // W1 [64k x 128n]
        int ln = idx & 31, ks = (idx >> 5) & 3, ns = idx >> 7;
        int tt = ln & 3, gg = ln >> 2;
        int n = ns * 8 + gg, k0 = ks * 16 + 2 * tt;
        w1f[idx] = make_uint2(
            pack_h2(W1[k0 * 128 + n],       W1[(k0 + 1) * 128 + n]),
            pack_h2(W1[(k0 + 8) * 128 + n], W1[(k0 + 9) * 128 + n]));
    }
    for (int idx = tid; idx < 8 * 8 * 32; idx += 512) {        // W2 [128k x 64n]
        int ln = idx & 31, ks = (idx >> 5) & 7, ns = idx >> 8;
        int tt = ln & 3, gg = ln >> 2;
        int n = ns * 8 + gg, k0 = ks * 16 + 2 * tt;
        w2f[idx] = make_uint2(
            pack_h2(W2[k0 * 64 + n],       W2[(k0 + 1) * 64 + n]),
            pack_h2(W2[(k0 + 8) * 64 + n], W2[(k0 + 9) * 64 + n]));
    }
    if (tid < 128) sb1[tid] = b1[tid];
    // 10/tau*log2e folded into bias; +5.287663 = -10*log2(ln2) from the log-base fold
    if (tid < 64)  sb2[tid] = fmaf(14.42695041f, b2[tid], 5.287663189f);
    __syncthreads();

    const int ntiles = (E + 255) >> 8;
    const int r0 = warp * 16;
    const int stride = gridDim.x;
    const int prow = lane >> 1;            // prefetch row 0..15
    const int phalf = (lane & 1) * 32;     // prefetch 128B half

    // warm first tile's lines
    if (blockIdx.x < ntiles) {
        int base = blockIdx.x << 8;
        int sp = src[min(base + r0 + prow, E - 1)];
        asm volatile("prefetch.global.L2 [%0];" :: "l"(x + (size_t)sp * 64 + phalf));
        asm volatile("prefetch.global.L2 [%0];"
                     :: "l"(u + (size_t)min(base + r0 + prow, E - 1) * 64 + phalf));
    }

    for (int tile = blockIdx.x; tile < ntiles; tile += stride) {
        const int base = tile << 8;
        const int e_lo = base + r0 + g, e_hi = e_lo + 8;
        __syncwarp();   // strip WAR: prev GEMM2 reads done before epi1 writes

        // ---- next-tile src index (LDG hidden under GEMM1; 1 reg)
        const int ntile = tile + stride;
        int s_next = 0;
        if (ntile < ntiles)
            s_next = src[min((ntile << 8) + r0 + prow, E - 1)];

        // ---- gather x[src] into fp16 A-fragments (16 LDG.64, L2-warm)
        uint32_t ax0[4], ax1[4], ax2[4], ax3[4];
        {
            int s_lo = src[min(e_lo, E - 1)];
            int s_hi = src[min(e_hi, E - 1)];
            const float* xlo = x + (size_t)s_lo * 64;
            const float* xhi = x + (size_t)s_hi * 64;
            #pragma unroll
            for (int ks = 0; ks < 4; ks++) {
                int c0 = ks * 16 + 2 * t, c1 = c0 + 8;
                float2 v0 = *(const float2*)(xlo + c0);
                float2 v1 = *(const float2*)(xhi + c0);
                float2 v2 = *(const float2*)(xlo + c1);
                float2 v3 = *(const float2*)(xhi + c1);
                ax0[ks] = pack_h2(v0.x, v0.y);
                ax1[ks] = pack_h2(v1.x, v1.y);
                ax2[ks] = pack_h2(v2.x, v2.y);
                ax3[ks] = pack_h2(v3.x, v3.y);
            }
        }

        // ---- GEMM1 in two passes of 8 n-slabs (4 k-steps of 16)
        #pragma unroll
        for (int pass = 0; pass < 2; pass++) {
            const int nbase = pass * 8;
            float acc[8][4];
            #pragma unroll
            for (int ns = 0; ns < 8; ns++)
                { acc[ns][0] = acc[ns][1] = acc[ns][2] = acc[ns][3] = 0.f; }

            #pragma unroll
            for (int ks = 0; ks < 4; ks++) {
                #pragma unroll
                for (int ns = 0; ns < 8; ns++) {
                    uint2 b = w1f[((nbase + ns) * 4 + ks) * 32 + lane];
                    mma16(acc[ns], ax0[ks], ax1[ks], ax2[ks], ax3[ks], b.x, b.y);
                }
            }
            // epi1: relu(+b1) -> fp16 strip (rows g, g+8; cols (nbase+ns)*8+2t)
            #pragma unroll
            for (int ns = 0; ns < 8; ns++) {
                int c = (nbase + ns) * 8 + 2 * t;
                float bx = sb1[c], by = sb1[c + 1];
                *(uint32_t*)(strip + g * STRIP_H + c) =
                    pack_h2(fmaxf(acc[ns][0] + bx, 0.f), fmaxf(acc[ns][1] + by, 0.f));
                *(uint32_t*)(strip + (g + 8) * STRIP_H + c) =
                    pack_h2(fmaxf(acc[ns][2] + bx, 0.f), fmaxf(acc[ns][3] + by, 0.f));
            }
        }
        __syncwarp();   // H visible to whole warp before GEMM2

        // ---- warm NEXT tile's x and u lines (no registers held)
        if (ntile < ntiles) {
            asm volatile("prefetch.global.L2 [%0];"
                         :: "l"(x + (size_t)s_next * 64 + phalf));
            asm volatile("prefetch.global.L2 [%0];"
                         :: "l"(u + (size_t)min((ntile << 8) + r0 + prow, E - 1) * 64 + phalf));
        }

        // ---- GEMM2: L[16,64] = H[16,128] @ W2 (8 k-steps of 16)
        float acc2[8][4];
        #pragma unroll
        for (int ns = 0; ns < 8; ns++)
            { acc2[ns][0] = acc2[ns][1] = acc2[ns][2] = acc2[ns][3] = 0.f; }
        #pragma unroll
        for (int ks = 0; ks < 8; ks++) {
            int c0 = ks * 16 + 2 * t, c1 = c0 + 8;
            uint32_t a0 = *(const uint32_t*)(strip + g * STRIP_H + c0);
            uint32_t a1 = *(const uint32_t*)(strip + (g + 8) * STRIP_H + c0);
            uint32_t a2 = *(const uint32_t*)(strip + g * STRIP_H + c1);
            uint32_t a3 = *(const uint32_t*)(strip + (g + 8) * STRIP_H + c1);
            #pragma unroll
            for (int ns = 0; ns < 8; ns++) {
                uint2 b = w2f[(ns * 8 + ks) * 32 + lane];
                mma16(acc2[ns], a0, a1, a2, a3, b.x, b.y);
            }
        }

        // ---- epi: gumbel softmax in log2 domain.
        //  a = 14.42695*logit + sb2' - 10*log2(min(-log2(u), 33.219))
        {
            const bool vlo = e_lo < E, vhi = e_hi < E;
            float alo[16], ahi[16];
            float mlo = -1e30f, mhi = -1e30f;
            #pragma unroll
            for (int ns = 0; ns < 8; ns++) {
                int c = ns * 8 + 2 * t;
                float b2x = sb2[c], b2y = sb2[c + 1];
                float2 ul = vlo ? *(const float2*)(u + (size_t)e_lo * 64 + c)
                               : make_float2(0.5f, 0.5f);
                float2 uh = vhi ? *(const float2*)(u + (size_t)e_hi * 64 + c)
                               : make_float2(0.5f, 0.5f);
                // p = -log2(u), clamped at 33.219 (== -ln(1e-10) in log2 units)
                float pl0 = fminf(-__log2f(ul.x), 33.21928095f);
                float pl1 = fminf(-__log2f(ul.y), 33.21928095f);
                float ph0 = fminf(-__log2f(uh.x), 33.21928095f);
                float ph1 = fminf(-__log2f(uh.y), 33.21928095f);
                float t00 = fmaf(acc2[ns][0], 14.42695041f, b2x);
                float t01 = fmaf(acc2[ns][1], 14.42695041f, b2y);
                float t10 = fmaf(acc2[ns][2], 14.42695041f, b2x);
                float t11 = fmaf(acc2[ns][3], 14.42695041f, b2y);
                alo[2*ns]   = fmaf(__log2f(pl0), -10.0f, t00);
                alo[2*ns+1] = fmaf(__log2f(pl1), -10.0f, t01);
                ahi[2*ns]   = fmaf(__log2f(ph0), -10.0f, t10);
                ahi[2*ns+1] = fmaf(__log2f(ph1), -10.0f, t11);
                mlo = fmaxf(mlo, fmaxf(alo[2*ns], alo[2*ns+1]));
                mhi = fmaxf(mhi, fmaxf(ahi[2*ns], ahi[2*ns+1]));
            }
            mlo = fmaxf(mlo, __shfl_xor_sync(FULL, mlo, 1));
            mlo = fmaxf(mlo, __shfl_xor_sync(FULL, mlo, 2));
            mhi = fmaxf(mhi, __shfl_xor_sync(FULL, mhi, 1));
            mhi = fmaxf(mhi, __shfl_xor_sync(FULL, mhi, 2));
            float slo = 0.f, shi = 0.f;
            #pragma unroll
            for (int i = 0; i < 16; i++) {
                float dl = alo[i] - mlo, dh = ahi[i] - mhi;
                // 2^-20 < 1e-6 cutoff: predicate off the MUFU + sum + atomic
                alo[i] = (dl > -20.f) ? exp2f(dl) : 0.f;
                ahi[i] = (dh > -20.f) ? exp2f(dh) : 0.f;
                slo += alo[i]; shi += ahi[i];
            }
            slo += __shfl_xor_sync(FULL, slo, 1);
            slo += __shfl_xor_sync(FULL, slo, 2);
            shi += __shfl_xor_sync(FULL, shi, 1);
            shi += __shfl_xor_sync(FULL, shi, 2);
            float ilo = __fdividef(1.0f, slo), ihi = __fdividef(1.0f, shi);
            // softmax strictly positive -> int compare == float compare.
            // skip values < 1e-6: y abs error <= 1e-6, invisible at 1e-3 rel_err
            if (vlo) {
                int* yp = (int*)(g_y + (size_t)dst[e_lo] * 64);
                #pragma unroll
                for (int ns = 0; ns < 8; ns++) {
                    float v0 = alo[2*ns] * ilo, v1 = alo[2*ns+1] * ilo;
                    if (v0 > 1e-6f) atomicMax(yp + ns*8 + 2*t,     __float_as_int(v0));
                    if (v1 > 1e-6f) atomicMax(yp + ns*8 + 2*t + 1, __float_as_int(v1));
                }
            }
            if (vhi) {
                int* yp = (int*)(g_y + (size_t)dst[e_hi] * 64);
                #pragma unroll
                for (int ns = 0; ns < 8; ns++) {
                    float v0 = ahi[2*ns] * ihi, v1 = ahi[2*ns+1] * ihi;
                    if (v0 > 1e-6f) atomicMax(yp + ns*8 + 2*t,     __float_as_int(v0));
                    if (v1 > 1e-6f) atomicMax(yp + ns*8 + 2*t + 1, __float_as_int(v1));
                }
            }
        }
    }
}

// ---------------------------------------------------------------------------
// node kernel (mma.sync tf32): 8 warps/CTA, warp = 16 nodes  (unchanged)
// ---------------------------------------------------------------------------
__global__ void __launch_bounds__(256, 1)
node_kernel(const float* __restrict__ x,
            const float* __restrict__ z,
            const float* __restrict__ bdec,
            const float* __restrict__ bih,
            const float* __restrict__ bhh,
            float* __restrict__ out,
            int N, int HALF, int two)
{
    extern __shared__ float nsm[];
    const int tid = threadIdx.x, warp = tid >> 5, lane = tid & 31;
    const int t = lane & 3, g = lane >> 2;

    float* sbr   = nsm + NOD_BR;
    float* sbin  = nsm + NOD_BIN;
    float* sbhn  = nsm + NOD_BHN;
    float* sbdec = nsm + NOD_BDEC;
    if (tid < 128) sbr[tid] = bih[tid] + bhh[tid];
    if (tid < 64)  { sbin[tid] = bih[128 + tid]; sbhn[tid] = bhh[128 + tid]; }
    if (tid < 128) sbdec[tid] = bdec[tid];
    __syncthreads();

    const int nb = (blockIdx.x * 8 + warp) * 16;
    if (nb >= N) return;

    float* strip = nsm + NOD_STRIP + warp * 3136;   // 16 x 196: x | dec
    float* yb    = nsm + NOD_YB    + warp * 1088;   // 16 x 68 tf32
    float* zb    = nsm + NOD_ZB    + warp * 1088;   // 16 x 68 fp32

    // ---- load x (tf32), y (tf32), z (fp32)
    {
        int r = lane >> 1, ch = (lane & 1) * 32;
        int n = min(nb + r, N - 1);
        const float4* xp = (const float4*)(x + (size_t)n * 64 + ch);
        const float4* yp = (const float4*)(g_y + (size_t)n * 64 + ch);
        const float4* zp = (const float4*)(z + (size_t)n * 64 + ch);
        float* sx = strip + r * 196 + ch;
        float* sy = yb + r * 68 + ch;
        float* sz = zb + r * 68 + ch;
        #pragma unroll
        for (int i = 0; i < 8; i++) {
            float4 vx = xp[i], vy = yp[i], vz = zp[i];
            sx[i*4+0] = tf32f(vx.x); sx[i*4+1] = tf32f(vx.y);
            sx[i*4+2] = tf32f(vx.z); sx[i*4+3] = tf32f(vx.w);
            sy[i*4+0] = tf32f(vy.x); sy[i*4+1] = tf32f(vy.y);
            sy[i*4+2] = tf32f(vy.z); sy[i*4+3] = tf32f(vy.w);
            *(float4*)(sz + i*4) = vz;
        }
    }
    __syncwarp();

    // ---- dec GEMM: 16 accs, ks-outer
    {
        float acc[16][4];
        #pragma unroll
        for (int ns = 0; ns < 16; ns++) {
            int c = ns * 8 + 2 * t;
            acc[ns][0] = sbdec[c]; acc[ns][1] = sbdec[c + 1];
            acc[ns][2] = sbdec[c]; acc[ns][3] = sbdec[c + 1];
        }
        for (int ks = 0; ks < 8; ks++) {
            uint32_t a0 = __float_as_uint(yb[g * 68 + ks * 8 + t]);
            uint32_t a1 = __float_as_uint(yb[(g + 8) * 68 + ks * 8 + t]);
            uint32_t a2 = __float_as_uint(yb[g * 68 + ks * 8 + t + 4]);
            uint32_t a3 = __float_as_uint(yb[(g + 8) * 68 + ks * 8 + t + 4]);
            #pragma unroll
            for (int ns = 0; ns < 16; ns++) {
                float2 b = __ldg(&g_WdecF[(ns * 8 + ks) * 32 + lane]);
                mma8(acc[ns], a0, a1, a2, a3,
                     __float_as_uint(b.x), __float_as_uint(b.y));
            }
        }
        #pragma unroll
        for (int ns = 0; ns < 16; ns++) {
            int c = 64 + ns * 8 + 2 * t;
            strip[g * 196 + c]           = tf32f(fmaxf(acc[ns][0], 0.f));
            strip[g * 196 + c + 1]       = tf32f(fmaxf(acc[ns][1], 0.f));
            strip[(g + 8) * 196 + c]     = tf32f(fmaxf(acc[ns][2], 0.f));
            strip[(g + 8) * 196 + c + 1] = tf32f(fmaxf(acc[ns][3], 0.f));
        }
    }
    __syncwarp();

    // ---- gate passes
    float rg[8][4], zg[8][4], ai[8][4], ah[8][4];

    #pragma unroll
    for (int p = 0; p < 2; p++) {               // p=0: r gate, p=1: z gate
        const int ns0 = p * 8;
        float acc[8][4];
        #pragma unroll
        for (int ns = 0; ns < 8; ns++) {
            int c = (ns0 + ns) * 8 + 2 * t;
            acc[ns][0] = sbr[c]; acc[ns][1] = sbr[c + 1];
            acc[ns][2] = sbr[c]; acc[ns][3] = sbr[c + 1];
        }
        for (int ks = 0; ks < 24; ks++) {       // gi: A = strip(x|dec)
            uint32_t a0 = __float_as_uint(strip[g * 196 + ks * 8 + t]);
            uint32_t a1 = __float_as_uint(strip[(g + 8) * 196 + ks * 8 + t]);
            uint32_t a2 = __float_as_uint(strip[g * 196 + ks * 8 + t + 4]);
            uint32_t a3 = __float_as_uint(strip[(g + 8) * 196 + ks * 8 + t + 4]);
            #pragma unroll
            for (int ns = 0; ns < 8; ns++) {
                float2 b = __ldg(&g_WihF[((ns0 + ns) * 24 + ks) * 32 + lane]);
                mma8(acc[ns], a0, a1, a2, a3,
                     __float_as_uint(b.x), __float_as_uint(b.y));
            }
        }
        for (int ks = 0; ks < 8; ks++) {        // gh: A = z (cvt tf32)
            uint32_t a0 = cvt_tf32(zb[g * 68 + ks * 8 + t]);
            uint32_t a1 = cvt_tf32(zb[(g + 8) * 68 + ks * 8 + t]);
            uint32_t a2 = cvt_tf32(zb[g * 68 + ks * 8 + t + 4]);
            uint32_t a3 = cvt_tf32(zb[(g + 8) * 68 + ks * 8 + t + 4]);
            #pragma unroll
            for (int ns = 0; ns < 8; ns++) {
                float2 b = __ldg(&g_WhhF[((ns0 + ns) * 8 + ks) * 32 + lane]);
                mma8(acc[ns], a0, a1, a2, a3,
                     __float_as_uint(b.x), __float_as_uint(b.y));
            }
        }
        #pragma unroll
        for (int ns = 0; ns < 8; ns++)
            #pragma unroll
            for (int q = 0; q < 4; q++) {
                float s = sigmoidf(acc[ns][q]);
                if (p == 0) rg[ns][q] = s; else zg[ns][q] = s;
            }
    }

    // n gate: i_n and h_n separate
    #pragma unroll
    for (int ns = 0; ns < 8; ns++) {
        int c = ns * 8 + 2 * t;
        ai[ns][0] = sbin[c]; ai[ns][1] = sbin[c + 1];
        ai[ns][2] = sbin[c]; ai[ns][3] = sbin[c + 1];
        ah[ns][0] = sbhn[c]; ah[ns][1] = sbhn[c + 1];
        ah[ns][2] = sbhn[c]; ah[ns][3] = sbhn[c + 1];
    }
    for (int ks = 0; ks < 24; ks++) {
        uint32_t a0 = __float_as_uint(strip[g * 196 + ks * 8 + t]);
        uint32_t a1 = __float_as_uint(strip[(g + 8) * 196 + ks * 8 + t]);
        uint32_t a2 = __float_as_uint(strip[g * 196 + ks * 8 + t + 4]);
        uint32_t a3 = __float_as_uint(strip[(g + 8) * 196 + ks * 8 + t + 4]);
        #pragma unroll
        for (int ns = 0; ns < 8; ns++) {
            float2 b = __ldg(&g_WihF[((16 + ns) * 24 + ks) * 32 + lane]);
            mma8(ai[ns], a0, a1, a2, a3,
                 __float_as_uint(b.x), __float_as_uint(b.y));
        }
    }
    for (int ks = 0; ks < 8; ks++) {
        uint32_t a0 = cvt_tf32(zb[g * 68 + ks * 8 + t]);
        uint32_t a1 = cvt_tf32(zb[(g + 8) * 68 + ks * 8 + t]);
        uint32_t a2 = cvt_tf32(zb[g * 68 + ks * 8 + t + 4]);
        uint32_t a3 = cvt_tf32(zb[(g + 8) * 68 + ks * 8 + t + 4]);
        #pragma unroll
        for (int ns = 0; ns < 8; ns++) {
            float2 b = __ldg(&g_WhhF[((16 + ns) * 8 + ks) * 32 + lane]);
            mma8(ah[ns], a0, a1, a2, a3,
                 __float_as_uint(b.x), __float_as_uint(b.y));
        }
    }

    // ---- combine gates + write (rows nb+g, nb+g+8; cols ns*8+2t, +1)
    const int R0 = nb + g, R1 = nb + g + 8;
    #pragma unroll
    for (int ns = 0; ns < 8; ns++) {
        int o = ns * 8 + 2 * t;
        float n00 = tanhf(ai[ns][0] + rg[ns][0] * ah[ns][0]);
        float n01 = tanhf(ai[ns][1] + rg[ns][1] * ah[ns][1]);
        float n10 = tanhf(ai[ns][2] + rg[ns][2] * ah[ns][2]);
        float n11 = tanhf(ai[ns][3] + rg[ns][3] * ah[ns][3]);
        float z00 = zb[g * 68 + o],       z01 = zb[g * 68 + o + 1];
        float z10 = zb[(g + 8) * 68 + o], z11 = zb[(g + 8) * 68 + o + 1];
        float h00 = (1.f - zg[ns][0]) * n00 + zg[ns][0] * z00;
        float h01 = (1.f - zg[ns][1]) * n01 + zg[ns][1] * z01;
        float h10 = (1.f - zg[ns][2]) * n10 + zg[ns][2] * z10;
        float h11 = (1.f - zg[ns][3]) * n11 + zg[ns][3] * z11;
        if (R0 < N) {
            *(float2*)(out + (size_t)R0 * 64 + o) = make_float2(h00, h01);
            if (two) *(float2*)(out + HALF + (size_t)R0 * 64 + o) = make_float2(h00, h01);
        }
        if (R1 < N) {
            *(float2*)(out + (size_t)R1 * 64 + o) = make_float2(h10, h11);
            if (two) *(float2*)(out + HALF + (size_t)R1 * 64 + o) = make_float2(h10, h11);
        }
    }
}

// ---------------------------------------------------------------------------
// launch
// inputs: x, z, src, dst, u, W_enc1, b_enc1, W_enc2, b_enc2,
//         W_dec, b_dec, W_ih, b_ih, W_hh, b_hh
// ---------------------------------------------------------------------------
extern "C" void kernel_launch(void* const* d_in, const int* in_sizes, int n_in,
                              void* d_out, int out_size)
{
    const float* x     = (const float*)d_in[0];
    const float* z     = (const float*)d_in[1];
    const int*   src   = (const int*)  d_in[2];
    const int*   dst   = (const int*)  d_in[3];
    const float* u     = (const float*)d_in[4];
    const float* W1    = (const float*)d_in[5];
    const float* b1    = (const float*)d_in[6];
    const float* W2    = (const float*)d_in[7];
    const float* b2    = (const float*)d_in[8];
    const float* Wdec  = (const float*)d_in[9];
    const float* bdec  = (const float*)d_in[10];
    const float* Wih   = (const float*)d_in[11];
    const float* bih   = (const float*)d_in[12];
    const float* Whh   = (const float*)d_in[13];
    const float* bhh   = (const float*)d_in[14];

    const int N = in_sizes[0] / FDIM;
    const int E = in_sizes[2];
    float* out = (float*)d_out;
    const int HALF = N * OUTF;
    const int two = (out_size >= 2 * HALF) ? 1 : 0;

    // init mailbox + fragment packs
    {
        int total = N * MSG;
        init_kernel<<<(total + 255) / 256, 256>>>(Wih, Whh, Wdec, N);
    }

    // edge kernel: persistent mma.sync fp16 (m16n8k16)
    {
        cudaFuncSetAttribute(edge_mma_kernel,
                             cudaFuncAttributeMaxDynamicSharedMemorySize, SMEM_EDGE);
        edge_mma_kernel<<<148, 512, SMEM_EDGE>>>(x, src, dst, u, W1, b1, W2, b2, E);
    }

    // node kernel: mma.sync tf32
    {
        cudaFuncSetAttribute(node_kernel,
                             cudaFuncAttributeMaxDynamicSharedMemorySize, SMEM_NODE);
        int blocks = (N + 127) / 128;
        node_kernel<<<blocks, 256, SMEM_NODE>>>(x, z, bdec, bih, bhh, out, N, HALF, two);
    }
}

// round 16
// speedup vs baseline: 2.3540x; 1.1778x over previous
#include <cuda_runtime.h>
#include <cuda_fp16.h>
#include <math.h>
#include <stdint.h>

#define FDIM 64
#define HIDD 128
#define MSG  64
#define OUTF 64
#define NMAX 50000

// scratch (no cudaMalloc allowed)
__device__ float g_y[NMAX * MSG];            // mailbox max, 12.8 MB
__device__ uint2 g_WdecH[16 * 4 * 32];       // fp16 mma B-frags for Wdec
__device__ uint2 g_WihH[24 * 12 * 32];       // fp16 mma B-frags for W_ih
__device__ uint2 g_WhhH[24 * 4 * 32];        // fp16 mma B-frags for W_hh

// ===========================================================================
// helpers
// ===========================================================================
__device__ __forceinline__ uint32_t pack_h2(float a, float b) {
    __half2 h = __floats2half2_rn(a, b);
    return *reinterpret_cast<uint32_t*>(&h);
}
// D += A(16x16) * B(16x8), fp16 inputs, f32 accum (full-rate HMMA)
__device__ __forceinline__ void mma16(float* c, uint32_t a0, uint32_t a1,
                                      uint32_t a2, uint32_t a3,
                                      uint32_t b0, uint32_t b1) {
    asm volatile(
        "mma.sync.aligned.m16n8k16.row.col.f32.f16.f16.f32 "
        "{%0,%1,%2,%3}, {%4,%5,%6,%7}, {%8,%9}, {%0,%1,%2,%3};"
        : "+f"(c[0]), "+f"(c[1]), "+f"(c[2]), "+f"(c[3])
        : "r"(a0), "r"(a1), "r"(a2), "r"(a3), "r"(b0), "r"(b1));
}
__device__ __forceinline__ float sigmoidf(float v) {
    return __fdividef(1.0f, 1.0f + __expf(-v));
}

// edge kernel smem layout (bytes)
#define OFF_W1F   0                    // 16 ns x 4 ks x 32 lane x uint2 = 16KB
#define OFF_W2F   16384                // 8 ns x 8 ks x 32 lane x uint2 = 16KB
#define OFF_SB1   32768                // 128 f
#define OFF_SB2   33280                // 64 f  (14.42695*b2 + 5.28766 folded)
#define OFF_STRIP 33536                // 16 warps x (16 rows x 272B) fp16 H
#define STRIP_B   4352                 // bytes per warp strip
#define STRIP_H   136                  // halves per row (128 + 8 pad)
#define SMEM_EDGE (OFF_STRIP + 16 * STRIP_B)   // 103168

// node kernel smem layout (bytes)
#define NB_STRIP  0                    // 8 warps x 16 rows x 400B (x|dec fp16, 200 halves)
#define NB_YB     51200                // 8 warps x 16 rows x 144B (y fp16, 72 halves)
#define NB_ZB     69632                // 8 warps x 16 rows x 272B (z fp32, 68 floats)
#define NB_BR     104448               // 128 f: bih+bhh (r,z gates)
#define NB_BIN    104960               // 64 f
#define NB_BHN    105216               // 64 f
#define NB_BDEC   105472               // 128 f
#define SMEM_NODE 105984
#define NSTRIP_H  200                  // halves per strip row
#define NYB_H     72                   // halves per yb row
#define NZB_F     68                   // floats per zb row

// ---------------------------------------------------------------------------
// init: zero mailbox + pack node-GEMM fp16 weight fragments
//   b0 = {B[k0][n], B[k0+1][n]}, b1 = {B[k0+8][n], B[k0+9][n]}, k0 = ks*16+2t
// ---------------------------------------------------------------------------
__global__ void init_kernel(const float* __restrict__ W_ih,
                            const float* __restrict__ W_hh,
                            const float* __restrict__ Wdec, int N)
{
    int idx = blockIdx.x * blockDim.x + threadIdx.x;
    if (idx < N * MSG) g_y[idx] = 0.0f;
    int lane = idx & 31, g = lane >> 2, t = lane & 3;
    if (idx < 16 * 4 * 32) {                 // WdecH: B[k=j][n=h] = Wdec[j*128+h]
        int ks = (idx >> 5) & 3, ns = idx >> 7;
        int n = ns * 8 + g, k0 = ks * 16 + 2 * t;
        g_WdecH[idx] = make_uint2(
            pack_h2(Wdec[k0 * 128 + n],       Wdec[(k0 + 1) * 128 + n]),
            pack_h2(Wdec[(k0 + 8) * 128 + n], Wdec[(k0 + 9) * 128 + n]));
    }
    if (idx < 24 * 12 * 32) {                // WihH: B[k=i][n=o] = W_ih[o*192+i]
        int ks = (idx >> 5) % 12, ns = (idx >> 5) / 12;
        int n = ns * 8 + g, k0 = ks * 16 + 2 * t;
        g_WihH[idx] = make_uint2(
            pack_h2(W_ih[n * 192 + k0],     W_ih[n * 192 + k0 + 1]),
            pack_h2(W_ih[n * 192 + k0 + 8], W_ih[n * 192 + k0 + 9]));
    }
    if (idx < 24 * 4 * 32) {                 // WhhH: B[k=j][n=o] = W_hh[o*64+j]
        int ks = (idx >> 5) & 3, ns = idx >> 7;
        int n = ns * 8 + g, k0 = ks * 16 + 2 * t;
        g_WhhH[idx] = make_uint2(
            pack_h2(W_hh[n * 64 + k0],     W_hh[n * 64 + k0 + 1]),
            pack_h2(W_hh[n * 64 + k0 + 8], W_hh[n * 64 + k0 + 9]));
    }
}

// ---------------------------------------------------------------------------
// edge kernel (mma.sync fp16 m16n8k16): persistent, tile = 256 edges, warp = 16
//   (unchanged from R14 — the 250us WIN)
// ---------------------------------------------------------------------------
__global__ void __launch_bounds__(512, 1)
edge_mma_kernel(const float* __restrict__ x, const int* __restrict__ src,
                const int* __restrict__ dst, const float* __restrict__ u,
                const float* __restrict__ W1, const float* __restrict__ b1,
                const float* __restrict__ W2, const float* __restrict__ b2,
                int E)
{
    extern __shared__ unsigned char smraw[];
    uint2* w1f = (uint2*)(smraw + OFF_W1F);
    uint2* w2f = (uint2*)(smraw + OFF_W2F);
    float* sb1 = (float*)(smraw + OFF_SB1);
    float* sb2 = (float*)(smraw + OFF_SB2);

    const int tid = threadIdx.x;
    const int warp = tid >> 5, lane = tid & 31;
    const int t = lane & 3, g = lane >> 2;
    const unsigned FULL = 0xffffffffu;
    __half* strip = (__half*)(smraw + OFF_STRIP + warp * STRIP_B);

    // ---- pack weights into m16n8k16 B-fragment order (fp16), once
    for (int idx = tid; idx < 16 * 4 * 32; idx += 512) {       // W1 [64k x 128n]
        int ln = idx & 31, ks = (idx >> 5) & 3, ns = idx >> 7;
        int tt = ln & 3, gg = ln >> 2;
        int n = ns * 8 + gg, k0 = ks * 16 + 2 * tt;
        w1f[idx] = make_uint2(
            pack_h2(W1[k0 * 128 + n],       W1[(k0 + 1) * 128 + n]),
            pack_h2(W1[(k0 + 8) * 128 + n], W1[(k0 + 9) * 128 + n]));
    }
    for (int idx = tid; idx < 8 * 8 * 32; idx += 512) {        // W2 [128k x 64n]
        int ln = idx & 31, ks = (idx >> 5) & 7, ns = idx >> 8;
        int tt = ln & 3, gg = ln >> 2;
        int n = ns * 8 + gg, k0 = ks * 16 + 2 * tt;
        w2f[idx] = make_uint2(
            pack_h2(W2[k0 * 64 + n],       W2[(k0 + 1) * 64 + n]),
            pack_h2(W2[(k0 + 8) * 64 + n], W2[(k0 + 9) * 64 + n]));
    }
    if (tid < 128) sb1[tid] = b1[tid];
    // 10/tau*log2e folded into bias; +5.287663 = -10*log2(ln2) from the log-base fold
    if (tid < 64)  sb2[tid] = fmaf(14.42695041f, b2[tid], 5.287663189f);
    __syncthreads();

    const int ntiles = (E + 255) >> 8;
    const int r0 = warp * 16;
    const int stride = gridDim.x;
    const int prow = lane >> 1;            // prefetch row 0..15
    const int phalf = (lane & 1) * 32;     // prefetch 128B half

    // warm first tile's lines
    if (blockIdx.x < ntiles) {
        int base = blockIdx.x << 8;
        int sp = src[min(base + r0 + prow, E - 1)];
        asm volatile("prefetch.global.L2 [%0];" :: "l"(x + (size_t)sp * 64 + phalf));
        asm volatile("prefetch.global.L2 [%0];"
                     :: "l"(u + (size_t)min(base + r0 + prow, E - 1) * 64 + phalf));
    }

    for (int tile = blockIdx.x; tile < ntiles; tile += stride) {
        const int base = tile << 8;
        const int e_lo = base + r0 + g, e_hi = e_lo + 8;
        __syncwarp();   // strip WAR: prev GEMM2 reads done before epi1 writes

        // ---- next-tile src index (LDG hidden under GEMM1; 1 reg)
        const int ntile = tile + stride;
        int s_next = 0;
        if (ntile < ntiles)
            s_next = src[min((ntile << 8) + r0 + prow, E - 1)];

        // ---- gather x[src] into fp16 A-fragments (16 LDG.64, L2-warm)
        uint32_t ax0[4], ax1[4], ax2[4], ax3[4];
        {
            int s_lo = src[min(e_lo, E - 1)];
            int s_hi = src[min(e_hi, E - 1)];
            const float* xlo = x + (size_t)s_lo * 64;
            const float* xhi = x + (size_t)s_hi * 64;
            #pragma unroll
            for (int ks = 0; ks < 4; ks++) {
                int c0 = ks * 16 + 2 * t, c1 = c0 + 8;
                float2 v0 = *(const float2*)(xlo + c0);
                float2 v1 = *(const float2*)(xhi + c0);
                float2 v2 = *(const float2*)(xlo + c1);
                float2 v3 = *(const float2*)(xhi + c1);
                ax0[ks] = pack_h2(v0.x, v0.y);
                ax1[ks] = pack_h2(v1.x, v1.y);
                ax2[ks] = pack_h2(v2.x, v2.y);
                ax3[ks] = pack_h2(v3.x, v3.y);
            }
        }

        // ---- GEMM1 in two passes of 8 n-slabs (4 k-steps of 16)
        #pragma unroll
        for (int pass = 0; pass < 2; pass++) {
            const int nbase = pass * 8;
            float acc[8][4];
            #pragma unroll
            for (int ns = 0; ns < 8; ns++)
                { acc[ns][0] = acc[ns][1] = acc[ns][2] = acc[ns][3] = 0.f; }

            #pragma unroll
            for (int ks = 0; ks < 4; ks++) {
                #pragma unroll
                for (int ns = 0; ns < 8; ns++) {
                    uint2 b = w1f[((nbase + ns) * 4 + ks) * 32 + lane];
                    mma16(acc[ns], ax0[ks], ax1[ks], ax2[ks], ax3[ks], b.x, b.y);
                }
            }
            // epi1: relu(+b1) -> fp16 strip (rows g, g+8; cols (nbase+ns)*8+2t)
            #pragma unroll
            for (int ns = 0; ns < 8; ns++) {
                int c = (nbase + ns) * 8 + 2 * t;
                float bx = sb1[c], by = sb1[c + 1];
                *(uint32_t*)(strip + g * STRIP_H + c) =
                    pack_h2(fmaxf(acc[ns][0] + bx, 0.f), fmaxf(acc[ns][1] + by, 0.f));
                *(uint32_t*)(strip + (g + 8) * STRIP_H + c) =
                    pack_h2(fmaxf(acc[ns][2] + bx, 0.f), fmaxf(acc[ns][3] + by, 0.f));
            }
        }
        __syncwarp();   // H visible to whole warp before GEMM2

        // ---- warm NEXT tile's x and u lines (no registers held)
        if (ntile < ntiles) {
            asm volatile("prefetch.global.L2 [%0];"
                         :: "l"(x + (size_t)s_next * 64 + phalf));
            asm volatile("prefetch.global.L2 [%0];"
                         :: "l"(u + (size_t)min((ntile << 8) + r0 + prow, E - 1) * 64 + phalf));
        }

        // ---- GEMM2: L[16,64] = H[16,128] @ W2 (8 k-steps of 16)
        float acc2[8][4];
        #pragma unroll
        for (int ns = 0; ns < 8; ns++)
            { acc2[ns][0] = acc2[ns][1] = acc2[ns][2] = acc2[ns][3] = 0.f; }
        #pragma unroll
        for (int ks = 0; ks < 8; ks++) {
            int c0 = ks * 16 + 2 * t, c1 = c0 + 8;
            uint32_t a0 = *(const uint32_t*)(strip + g * STRIP_H + c0);
            uint32_t a1 = *(const uint32_t*)(strip + (g + 8) * STRIP_H + c0);
            uint32_t a2 = *(const uint32_t*)(strip + g * STRIP_H + c1);
            uint32_t a3 = *(const uint32_t*)(strip + (g + 8) * STRIP_H + c1);
            #pragma unroll
            for (int ns = 0; ns < 8; ns++) {
                uint2 b = w2f[(ns * 8 + ks) * 32 + lane];
                mma16(acc2[ns], a0, a1, a2, a3, b.x, b.y);
            }
        }

        // ---- epi: gumbel softmax in log2 domain.
        {
            const bool vlo = e_lo < E, vhi = e_hi < E;
            float alo[16], ahi[16];
            float mlo = -1e30f, mhi = -1e30f;
            #pragma unroll
            for (int ns = 0; ns < 8; ns++) {
                int c = ns * 8 + 2 * t;
                float b2x = sb2[c], b2y = sb2[c + 1];
                float2 ul = vlo ? *(const float2*)(u + (size_t)e_lo * 64 + c)
                               : make_float2(0.5f, 0.5f);
                float2 uh = vhi ? *(const float2*)(u + (size_t)e_hi * 64 + c)
                               : make_float2(0.5f, 0.5f);
                // p = -log2(u), clamped at 33.219 (== -ln(1e-10) in log2 units)
                float pl0 = fminf(-__log2f(ul.x), 33.21928095f);
                float pl1 = fminf(-__log2f(ul.y), 33.21928095f);
                float ph0 = fminf(-__log2f(uh.x), 33.21928095f);
                float ph1 = fminf(-__log2f(uh.y), 33.21928095f);
                float t00 = fmaf(acc2[ns][0], 14.42695041f, b2x);
                float t01 = fmaf(acc2[ns][1], 14.42695041f, b2y);
                float t10 = fmaf(acc2[ns][2], 14.42695041f, b2x);
                float t11 = fmaf(acc2[ns][3], 14.42695041f, b2y);
                alo[2*ns]   = fmaf(__log2f(pl0), -10.0f, t00);
                alo[2*ns+1] = fmaf(__log2f(pl1), -10.0f, t01);
                ahi[2*ns]   = fmaf(__log2f(ph0), -10.0f, t10);
                ahi[2*ns+1] = fmaf(__log2f(ph1), -10.0f, t11);
                mlo = fmaxf(mlo, fmaxf(alo[2*ns], alo[2*ns+1]));
                mhi = fmaxf(mhi, fmaxf(ahi[2*ns], ahi[2*ns+1]));
            }
            mlo = fmaxf(mlo, __shfl_xor_sync(FULL, mlo, 1));
            mlo = fmaxf(mlo, __shfl_xor_sync(FULL, mlo, 2));
            mhi = fmaxf(mhi, __shfl_xor_sync(FULL, mhi, 1));
            mhi = fmaxf(mhi, __shfl_xor_sync(FULL, mhi, 2));
            float slo = 0.f, shi = 0.f;
            #pragma unroll
            for (int i = 0; i < 16; i++) {
                float dl = alo[i] - mlo, dh = ahi[i] - mhi;
                // 2^-20 < 1e-6 cutoff: predicate off the MUFU + sum + atomic
                alo[i] = (dl > -20.f) ? exp2f(dl) : 0.f;
                ahi[i] = (dh > -20.f) ? exp2f(dh) : 0.f;
                slo += alo[i]; shi += ahi[i];
            }
            slo += __shfl_xor_sync(FULL, slo, 1);
            slo += __shfl_xor_sync(FULL, slo, 2);
            shi += __shfl_xor_sync(FULL, shi, 1);
            shi += __shfl_xor_sync(FULL, shi, 2);
            float ilo = __fdividef(1.0f, slo), ihi = __fdividef(1.0f, shi);
            // softmax strictly positive -> int compare == float compare.
            // skip values < 1e-6: y abs error <= 1e-6, invisible at 1e-3 rel_err
            if (vlo) {
                int* yp = (int*)(g_y + (size_t)dst[e_lo] * 64);
                #pragma unroll
                for (int ns = 0; ns < 8; ns++) {
                    float v0 = alo[2*ns] * ilo, v1 = alo[2*ns+1] * ilo;
                    if (v0 > 1e-6f) atomicMax(yp + ns*8 + 2*t,     __float_as_int(v0));
                    if (v1 > 1e-6f) atomicMax(yp + ns*8 + 2*t + 1, __float_as_int(v1));
                }
            }
            if (vhi) {
                int* yp = (int*)(g_y + (size_t)dst[e_hi] * 64);
                #pragma unroll
                for (int ns = 0; ns < 8; ns++) {
                    float v0 = ahi[2*ns] * ihi, v1 = ahi[2*ns+1] * ihi;
                    if (v0 > 1e-6f) atomicMax(yp + ns*8 + 2*t,     __float_as_int(v0));
                    if (v1 > 1e-6f) atomicMax(yp + ns*8 + 2*t + 1, __float_as_int(v1));
                }
            }
        }
    }
}

// ---------------------------------------------------------------------------
// node kernel (mma.sync fp16 m16n8k16): 8 warps/CTA, warp = 16 nodes
//   dec = relu(y[16,64] @ Wdec + b)        (4 k-steps, 16 n-slabs)
//   gi  = [x|dec](16,192) @ Wih^T          (12 k-steps per gate pass)
//   gh  = z(16,64) @ Whh^T                 (4 k-steps, cvt fp32->fp16 on the fly)
//   GRU gates + output (z interpolation in fp32)
// ---------------------------------------------------------------------------
__global__ void __launch_bounds__(256, 1)
node_kernel(const float* __restrict__ x,
            const float* __restrict__ z,
            const float* __restrict__ bdec,
            const float* __restrict__ bih,
            const float* __restrict__ bhh,
            float* __restrict__ out,
            int N, int HALF, int two)
{
    extern __shared__ unsigned char nraw[];
    const int tid = threadIdx.x, warp = tid >> 5, lane = tid & 31;
    const int t = lane & 3, g = lane >> 2;

    float* sbr   = (float*)(nraw + NB_BR);
    float* sbin  = (float*)(nraw + NB_BIN);
    float* sbhn  = (float*)(nraw + NB_BHN);
    float* sbdec = (float*)(nraw + NB_BDEC);
    if (tid < 128) sbr[tid] = bih[tid] + bhh[tid];
    if (tid < 64)  { sbin[tid] = bih[128 + tid]; sbhn[tid] = bhh[128 + tid]; }
    if (tid < 128) sbdec[tid] = bdec[tid];
    __syncthreads();

    const int nb = (blockIdx.x * 8 + warp) * 16;
    if (nb >= N) return;

    __half* strip = (__half*)(nraw + NB_STRIP + warp * 16 * 400);  // 16 x 200 halves
    __half* yb    = (__half*)(nraw + NB_YB    + warp * 16 * 144);  // 16 x 72 halves
    float*  zb    = (float*) (nraw + NB_ZB    + warp * 16 * 272);  // 16 x 68 floats

    // ---- load x (fp16 -> strip cols 0..63), y (fp16), z (fp32)
    {
        int r = lane >> 1, ch = (lane & 1) * 32;
        int n = min(nb + r, N - 1);
        const float4* xp = (const float4*)(x + (size_t)n * 64 + ch);
        const float4* yp = (const float4*)(g_y + (size_t)n * 64 + ch);
        const float4* zp = (const float4*)(z + (size_t)n * 64 + ch);
        __half* sx = strip + r * NSTRIP_H + ch;
        __half* sy = yb + r * NYB_H + ch;
        float*  sz = zb + r * NZB_F + ch;
        #pragma unroll
        for (int i = 0; i < 8; i++) {
            float4 vx = xp[i], vy = yp[i], vz = zp[i];
            *(uint2*)(sx + i * 4) = make_uint2(pack_h2(vx.x, vx.y), pack_h2(vx.z, vx.w));
            *(uint2*)(sy + i * 4) = make_uint2(pack_h2(vy.x, vy.y), pack_h2(vy.z, vy.w));
            *(float4*)(sz + i * 4) = vz;
        }
    }
    __syncwarp();

    // ---- dec GEMM: 16 n-slabs, 4 k-steps; A = y (fp16)
    {
        float acc[16][4];
        #pragma unroll
        for (int ns = 0; ns < 16; ns++) {
            int c = ns * 8 + 2 * t;
            acc[ns][0] = sbdec[c]; acc[ns][1] = sbdec[c + 1];
            acc[ns][2] = sbdec[c]; acc[ns][3] = sbdec[c + 1];
        }
        #pragma unroll
        for (int ks = 0; ks < 4; ks++) {
            int c0 = ks * 16 + 2 * t, c1 = c0 + 8;
            uint32_t a0 = *(const uint32_t*)(yb + g * NYB_H + c0);
            uint32_t a1 = *(const uint32_t*)(yb + (g + 8) * NYB_H + c0);
            uint32_t a2 = *(const uint32_t*)(yb + g * NYB_H + c1);
            uint32_t a3 = *(const uint32_t*)(yb + (g + 8) * NYB_H + c1);
            #pragma unroll
            for (int ns = 0; ns < 16; ns++) {
                uint2 b = __ldg(&g_WdecH[(ns * 4 + ks) * 32 + lane]);
                mma16(acc[ns], a0, a1, a2, a3, b.x, b.y);
            }
        }
        #pragma unroll
        for (int ns = 0; ns < 16; ns++) {
            int c = 64 + ns * 8 + 2 * t;
            *(uint32_t*)(strip + g * NSTRIP_H + c) =
                pack_h2(fmaxf(acc[ns][0], 0.f), fmaxf(acc[ns][1], 0.f));
            *(uint32_t*)(strip + (g + 8) * NSTRIP_H + c) =
                pack_h2(fmaxf(acc[ns][2], 0.f), fmaxf(acc[ns][3], 0.f));
        }
    }
    __syncwarp();

    // ---- gate passes
    float rg[8][4], zg[8][4], ai[8][4], ah[8][4];

    #pragma unroll
    for (int p = 0; p < 2; p++) {               // p=0: r gate, p=1: z gate
        const int ns0 = p * 8;
        float acc[8][4];
        #pragma unroll
        for (int ns = 0; ns < 8; ns++) {
            int c = (ns0 + ns) * 8 + 2 * t;
            acc[ns][0] = sbr[c]; acc[ns][1] = sbr[c + 1];
            acc[ns][2] = sbr[c]; acc[ns][3] = sbr[c + 1];
        }
        #pragma unroll
        for (int ks = 0; ks < 12; ks++) {       // gi: A = strip(x|dec), k=192
            int c0 = ks * 16 + 2 * t, c1 = c0 + 8;
            uint32_t a0 = *(const uint32_t*)(strip + g * NSTRIP_H + c0);
            uint32_t a1 = *(const uint32_t*)(strip + (g + 8) * NSTRIP_H + c0);
            uint32_t a2 = *(const uint32_t*)(strip + g * NSTRIP_H + c1);
            uint32_t a3 = *(const uint32_t*)(strip + (g + 8) * NSTRIP_H + c1);
            #pragma unroll
            for (int ns = 0; ns < 8; ns++) {
                uint2 b = __ldg(&g_WihH[((ns0 + ns) * 12 + ks) * 32 + lane]);
                mma16(acc[ns], a0, a1, a2, a3, b.x, b.y);
            }
        }
        #pragma unroll
        for (int ks = 0; ks < 4; ks++) {        // gh: A = z (cvt fp32->fp16)
            int c0 = ks * 16 + 2 * t, c1 = c0 + 8;
            uint32_t a0 = pack_h2(zb[g * NZB_F + c0], zb[g * NZB_F + c0 + 1]);
            uint32_t a1 = pack_h2(zb[(g + 8) * NZB_F + c0], zb[(g + 8) * NZB_F + c0 + 1]);
            uint32_t a2 = pack_h2(zb[g * NZB_F + c1], zb[g * NZB_F + c1 + 1]);
            uint32_t a3 = pack_h2(zb[(g + 8) * NZB_F + c1], zb[(g + 8) * NZB_F + c1 + 1]);
            #pragma unroll
            for (int ns = 0; ns < 8; ns++) {
                uint2 b = __ldg(&g_WhhH[((ns0 + ns) * 4 + ks) * 32 + lane]);
                mma16(acc[ns], a0, a1, a2, a3, b.x, b.y);
            }
        }
        #pragma unroll
        for (int ns = 0; ns < 8; ns++)
            #pragma unroll
            for (int q = 0; q < 4; q++) {
                float s = sigmoidf(acc[ns][q]);
                if (p == 0) rg[ns][q] = s; else zg[ns][q] = s;
            }
    }

    // n gate: i_n and h_n separate accumulators
    #pragma unroll
    for (int ns = 0; ns < 8; ns++) {
        int c = ns * 8 + 2 * t;
        ai[ns][0] = sbin[c]; ai[ns][1] = sbin[c + 1];
        ai[ns][2] = sbin[c]; ai[ns][3] = sbin[c + 1];
        ah[ns][0] = sbhn[c]; ah[ns][1] = sbhn[c + 1];
        ah[ns][2] = sbhn[c]; ah[ns][3] = sbhn[c + 1];
    }
    #pragma unroll
    for (int ks = 0; ks < 12; ks++) {
        int c0 = ks * 16 + 2 * t, c1 = c0 + 8;
        uint32_t a0 = *(const uint32_t*)(strip + g * NSTRIP_H + c0);
        uint32_t a1 = *(const uint32_t*)(strip + (g + 8) * NSTRIP_H + c0);
        uint32_t a2 = *(const uint32_t*)(strip + g * NSTRIP_H + c1);
        uint32_t a3 = *(const uint32_t*)(strip + (g + 8) * NSTRIP_H + c1);
        #pragma unroll
        for (int ns = 0; ns < 8; ns++) {
            uint2 b = __ldg(&g_WihH[((16 + ns) * 12 + ks) * 32 + lane]);
            mma16(ai[ns], a0, a1, a2, a3, b.x, b.y);
        }
    }
    #pragma unroll
    for (int ks = 0; ks < 4; ks++) {
        int c0 = ks * 16 + 2 * t, c1 = c0 + 8;
        uint32_t a0 = pack_h2(zb[g * NZB_F + c0], zb[g * NZB_F + c0 + 1]);
        uint32_t a1 = pack_h2(zb[(g + 8) * NZB_F + c0], zb[(g + 8) * NZB_F + c0 + 1]);
        uint32_t a2 = pack_h2(zb[g * NZB_F + c1], zb[g * NZB_F + c1 + 1]);
        uint32_t a3 = pack_h2(zb[(g + 8) * NZB_F + c1], zb[(g + 8) * NZB_F + c1 + 1]);
        #pragma unroll
        for (int ns = 0; ns < 8; ns++) {
            uint2 b = __ldg(&g_WhhH[((16 + ns) * 4 + ks) * 32 + lane]);
            mma16(ah[ns], a0, a1, a2, a3, b.x, b.y);
        }
    }

    // ---- combine gates + write (rows nb+g, nb+g+8; cols ns*8+2t, +1)
    const int R0 = nb + g, R1 = nb + g + 8;
    #pragma unroll
    for (int ns = 0; ns < 8; ns++) {
        int o = ns * 8 + 2 * t;
        float n00 = tanhf(ai[ns][0] + rg[ns][0] * ah[ns][0]);
        float n01 = tanhf(ai[ns][1] + rg[ns][1] * ah[ns][1]);
        float n10 = tanhf(ai[ns][2] + rg[ns][2] * ah[ns][2]);
        float n11 = tanhf(ai[ns][3] + rg[ns][3] * ah[ns][3]);
        float z00 = zb[g * NZB_F + o],       z01 = zb[g * NZB_F + o + 1];
        float z10 = zb[(g + 8) * NZB_F + o], z11 = zb[(g + 8) * NZB_F + o + 1];
        float h00 = (1.f - zg[ns][0]) * n00 + zg[ns][0] * z00;
        float h01 = (1.f - zg[ns][1]) * n01 + zg[ns][1] * z01;
        float h10 = (1.f - zg[ns][2]) * n10 + zg[ns][2] * z10;
        float h11 = (1.f - zg[ns][3]) * n11 + zg[ns][3] * z11;
        if (R0 < N) {
            *(float2*)(out + (size_t)R0 * 64 + o) = make_float2(h00, h01);
            if (two) *(float2*)(out + HALF + (size_t)R0 * 64 + o) = make_float2(h00, h01);
        }
        if (R1 < N) {
            *(float2*)(out + (size_t)R1 * 64 + o) = make_float2(h10, h11);
            if (two) *(float2*)(out + HALF + (size_t)R1 * 64 + o) = make_float2(h10, h11);
        }
    }
}

// ---------------------------------------------------------------------------
// launch
// inputs: x, z, src, dst, u, W_enc1, b_enc1, W_enc2, b_enc2,
//         W_dec, b_dec, W_ih, b_ih, W_hh, b_hh
// ---------------------------------------------------------------------------
extern "C" void kernel_launch(void* const* d_in, const int* in_sizes, int n_in,
                              void* d_out, int out_size)
{
    const float* x     = (const float*)d_in[0];
    const float* z     = (const float*)d_in[1];
    const int*   src   = (const int*)  d_in[2];
    const int*   dst   = (const int*)  d_in[3];
    const float* u     = (const float*)d_in[4];
    const float* W1    = (const float*)d_in[5];
    const float* b1    = (const float*)d_in[6];
    const float* W2    = (const float*)d_in[7];
    const float* b2    = (const float*)d_in[8];
    const float* Wdec  = (const float*)d_in[9];
    const float* bdec  = (const float*)d_in[10];
    const float* Wih   = (const float*)d_in[11];
    const float* bih   = (const float*)d_in[12];
    const float* Whh   = (const float*)d_in[13];
    const float* bhh   = (const float*)d_in[14];

    const int N = in_sizes[0] / FDIM;
    const int E = in_sizes[2];
    float* out = (float*)d_out;
    const int HALF = N * OUTF;
    const int two = (out_size >= 2 * HALF) ? 1 : 0;

    // init mailbox + fp16 fragment packs
    {
        int total = N * MSG;
        init_kernel<<<(total + 255) / 256, 256>>>(Wih, Whh, Wdec, N);
    }

    // edge kernel: persistent mma.sync fp16 (m16n8k16)
    {
        cudaFuncSetAttribute(edge_mma_kernel,
                             cudaFuncAttributeMaxDynamicSharedMemorySize, SMEM_EDGE);
        edge_mma_kernel<<<148, 512, SMEM_EDGE>>>(x, src, dst, u, W1, b1, W2, b2, E);
    }

    // node kernel: mma.sync fp16 (m16n8k16)
    {
        cudaFuncSetAttribute(node_kernel,
                             cudaFuncAttributeMaxDynamicSharedMemorySize, SMEM_NODE);
        int blocks = (N + 127) / 128;
        node_kernel<<<blocks, 256, SMEM_NODE>>>(x, z, bdec, bih, bhh, out, N, HALF, two);
    }
}